// round 1
// baseline (speedup 1.0000x reference)
#include <cuda_runtime.h>
#include <math.h>

#define N_NODES 20000
#define N_EDGES 320000

// ---------------- device scratch (static, allocation-free) ----------------
__device__ int   g_e64;                 // 1 if edge_index is int64
__device__ int   g_cnt[N_NODES];        // in-degree histogram (excl. self loop)
__device__ int   g_ptr[N_NODES + 1];    // CSR row pointers (by destination)
__device__ int   g_cur[N_NODES];        // fill cursors
__device__ int   g_src[N_EDGES];        // CSR adjacency: source node per edge
__device__ float g_deg[N_NODES];        // degree incl. self loop (float)
__device__ float g_dinv[N_NODES];       // rsqrt(deg)
__device__ float g_agg[N_NODES * 256];  // pre-aggregation buffer (max 256 dims)
__device__ float g_bufA[N_NODES * 256]; // layer outputs (64 / 256)
__device__ float g_bufB[N_NODES * 512]; // layer outputs (128 / 512)
__device__ float g_h[N_NODES];          // layer-5 GEMM output (scalar per node)

// ---------------- edge access (int32 / int64 agnostic) ----------------
__device__ __forceinline__ int edge_at(const void* e, long long idx) {
    if (g_e64) return (int)((const long long*)e)[idx];
    return ((const int*)e)[idx];
}

__global__ void detect_dtype_kernel(const void* e) {
    // If data is int32 pairs misread as int64, hi word is a random node id
    // (nonzero w.p. 1 - 5e-5 per element) -> value >= 2^32.
    const long long* p = (const long long*)e;
    bool ok = true;
#pragma unroll
    for (int i = 0; i < 8; i++) {
        long long v = p[i];
        if (v < 0 || v >= N_NODES) ok = false;
    }
    g_e64 = ok ? 1 : 0;
}

__global__ void init_cnt_kernel() {
    int i = blockIdx.x * blockDim.x + threadIdx.x;
    if (i < N_NODES) g_cnt[i] = 0;
}

__global__ void histo_kernel(const void* e) {
    int i = blockIdx.x * blockDim.x + threadIdx.x;
    if (i < N_EDGES) {
        int dst = edge_at(e, (long long)N_EDGES + i);
        atomicAdd(&g_cnt[dst], 1);
    }
}

// single-block exclusive scan of g_cnt -> g_ptr
__global__ void scan_kernel() {
    __shared__ int sh[1024];
    __shared__ int carry;
    int t = threadIdx.x;
    if (t == 0) { carry = 0; g_ptr[0] = 0; }
    __syncthreads();
    for (int base = 0; base < N_NODES; base += 1024) {
        int i = base + t;
        int v = (i < N_NODES) ? g_cnt[i] : 0;
        sh[t] = v;
        __syncthreads();
        for (int off = 1; off < 1024; off <<= 1) {
            int add = (t >= off) ? sh[t - off] : 0;
            __syncthreads();
            sh[t] += add;
            __syncthreads();
        }
        if (i < N_NODES) g_ptr[i + 1] = carry + sh[t];
        __syncthreads();
        if (t == 1023) carry += sh[1023];
        __syncthreads();
    }
}

__global__ void node_init_kernel() {
    int i = blockIdx.x * blockDim.x + threadIdx.x;
    if (i < N_NODES) {
        float d = (float)(g_cnt[i] + 1);   // + self loop
        g_deg[i]  = d;
        g_dinv[i] = rsqrtf(d);
        g_cur[i]  = g_ptr[i];
    }
}

__global__ void fill_kernel(const void* e) {
    int i = blockIdx.x * blockDim.x + threadIdx.x;
    if (i < N_EDGES) {
        int src = edge_at(e, i);
        int dst = edge_at(e, (long long)N_EDGES + i);
        int pos = atomicAdd(&g_cur[dst], 1);
        g_src[pos] = src;
    }
}

// ---------------- aggregation: A[i] = (dinv_i * sum_e dinv_s X[s] + dinv_i^2 X[i]) / deg_i
// one warp per node, lane handles dims lane, lane+32, ...
template <int D>
__global__ void aggregate_kernel(const float* __restrict__ X, float* __restrict__ A,
                                 int mean_aggr) {
    int gtid = blockIdx.x * blockDim.x + threadIdx.x;
    int node = gtid >> 5;
    int lane = threadIdx.x & 31;
    if (node >= N_NODES) return;
    constexpr int R = (D + 31) / 32;
    float acc[R];
#pragma unroll
    for (int r = 0; r < R; r++) acc[r] = 0.f;
    int beg = g_ptr[node], end = g_ptr[node + 1];
    for (int p = beg; p < end; p++) {
        int s = g_src[p];
        float w = g_dinv[s];
        const float* xs = X + (long long)s * D;
#pragma unroll
        for (int r = 0; r < R; r++) {
            int dim = lane + 32 * r;
            if (dim < D) acc[r] += w * xs[dim];
        }
    }
    float di   = g_dinv[node];
    float selfw = di * di;
    float scale = mean_aggr ? (1.0f / g_deg[node]) : 1.0f;
    const float* xi = X + (long long)node * D;
    float* ao = A + (long long)node * D;
#pragma unroll
    for (int r = 0; r < R; r++) {
        int dim = lane + 32 * r;
        if (dim < D) ao[dim] = (di * acc[r] + selfw * xi[dim]) * scale;
    }
}

// ---------------- GEMM: C[M,N] = relu(A[M,K] @ B[K,N] + bias)  (fp32, tiled)
__global__ void gemm_bias_relu_kernel(const float* __restrict__ A,
                                      const float* __restrict__ B,
                                      const float* __restrict__ bias,
                                      float* __restrict__ C,
                                      int M, int K, int N, int do_relu) {
    const int BM = 64, BN = 64, BK = 16, TM = 4, TN = 4;
    __shared__ float As[BK][BM];
    __shared__ float Bs[BK][BN];
    int tid = threadIdx.x;             // 256 threads
    int tx = tid % 16;                 // 16 col-groups of TN
    int ty = tid / 16;                 // 16 row-groups of TM
    int rowBase = blockIdx.y * BM;
    int colBase = blockIdx.x * BN;
    float acc[TM][TN];
#pragma unroll
    for (int m = 0; m < TM; m++)
#pragma unroll
        for (int n = 0; n < TN; n++) acc[m][n] = 0.f;

    for (int k0 = 0; k0 < K; k0 += BK) {
#pragma unroll
        for (int i = 0; i < 4; i++) {
            int idx = tid + i * 256;        // 0..1023, BM*BK elems
            int r = idx / BK, kk = idx % BK;
            int gr = rowBase + r;
            As[kk][r] = (gr < M) ? A[(long long)gr * K + k0 + kk] : 0.f;
        }
#pragma unroll
        for (int i = 0; i < 4; i++) {
            int idx = tid + i * 256;        // BK*BN elems
            int kk = idx / BN, c = idx % BN;
            Bs[kk][c] = B[(long long)(k0 + kk) * N + colBase + c];
        }
        __syncthreads();
#pragma unroll
        for (int kk = 0; kk < BK; kk++) {
            float a[TM], b[TN];
#pragma unroll
            for (int m = 0; m < TM; m++) a[m] = As[kk][ty * TM + m];
#pragma unroll
            for (int n = 0; n < TN; n++) b[n] = Bs[kk][tx * TN + n];
#pragma unroll
            for (int m = 0; m < TM; m++)
#pragma unroll
                for (int n = 0; n < TN; n++) acc[m][n] += a[m] * b[n];
        }
        __syncthreads();
    }
#pragma unroll
    for (int m = 0; m < TM; m++) {
        int r = rowBase + ty * TM + m;
        if (r >= M) continue;
#pragma unroll
        for (int n = 0; n < TN; n++) {
            int c = colBase + tx * TN + n;
            float v = acc[m][n] + bias[c];
            if (do_relu) v = fmaxf(v, 0.f);
            C[(long long)r * N + c] = v;
        }
    }
}

// ---------------- layer 5: h[i] = X[i,:] . W5  (K=512), warp per row
__global__ void rowdot_kernel(const float* __restrict__ X, const float* __restrict__ W,
                              float* __restrict__ h) {
    int gtid = blockIdx.x * blockDim.x + threadIdx.x;
    int row = gtid >> 5;
    int lane = threadIdx.x & 31;
    if (row >= N_NODES) return;
    const float* xr = X + (long long)row * 512;
    float s = 0.f;
#pragma unroll
    for (int k = lane; k < 512; k += 32) s += xr[k] * W[k];
#pragma unroll
    for (int off = 16; off > 0; off >>= 1) s += __shfl_down_sync(0xffffffff, s, off);
    if (lane == 0) h[row] = s;
}

// ---------------- layer 5 post-aggregation (add aggr) + sigmoid
__global__ void final_agg_kernel(const float* __restrict__ h, const float* __restrict__ b5,
                                 float* __restrict__ out) {
    int i = blockIdx.x * blockDim.x + threadIdx.x;
    if (i >= N_NODES) return;
    float s = 0.f;
    int beg = g_ptr[i], end = g_ptr[i + 1];
    for (int p = beg; p < end; p++) {
        int src = g_src[p];
        s += g_dinv[src] * h[src];
    }
    float di = g_dinv[i];
    float v = di * s + di * di * h[i] + b5[0];
    out[i] = 1.f / (1.f + expf(-v));
}

// ---------------- launch ----------------
extern "C" void kernel_launch(void* const* d_in, const int* in_sizes, int n_in,
                              void* d_out, int out_size) {
    const float* x  = (const float*)d_in[0];
    const void*  ei = d_in[1];
    const float* W1 = (const float*)d_in[2],  *b1 = (const float*)d_in[3];
    const float* W2 = (const float*)d_in[4],  *b2 = (const float*)d_in[5];
    const float* W3 = (const float*)d_in[6],  *b3 = (const float*)d_in[7];
    const float* W4 = (const float*)d_in[8],  *b4 = (const float*)d_in[9];
    const float* W5 = (const float*)d_in[10], *b5 = (const float*)d_in[11];
    float* out = (float*)d_out;

    float *agg, *bufA, *bufB, *hbuf;
    cudaGetSymbolAddress((void**)&agg,  g_agg);
    cudaGetSymbolAddress((void**)&bufA, g_bufA);
    cudaGetSymbolAddress((void**)&bufB, g_bufB);
    cudaGetSymbolAddress((void**)&hbuf, g_h);

    const int TPB = 256;
    int nodeBlocks = (N_NODES + TPB - 1) / TPB;
    int edgeBlocks = (N_EDGES + TPB - 1) / TPB;
    int warpNodeBlocks = (N_NODES * 32 + TPB - 1) / TPB;

    // --- graph preprocessing (CSR by destination) ---
    detect_dtype_kernel<<<1, 1>>>(ei);
    init_cnt_kernel<<<nodeBlocks, TPB>>>();
    histo_kernel<<<edgeBlocks, TPB>>>(ei);
    scan_kernel<<<1, 1024>>>();
    node_init_kernel<<<nodeBlocks, TPB>>>();
    fill_kernel<<<edgeBlocks, TPB>>>(ei);

    dim3 g1(64 / 64, (N_NODES + 63) / 64);   // N=64
    dim3 g2(128 / 64, (N_NODES + 63) / 64);  // N=128
    dim3 g3(256 / 64, (N_NODES + 63) / 64);  // N=256
    dim3 g4(512 / 64, (N_NODES + 63) / 64);  // N=512

    // layer 1: agg(x:16) -> gemm 16x64
    aggregate_kernel<16><<<warpNodeBlocks, TPB>>>(x, agg, 1);
    gemm_bias_relu_kernel<<<g1, 256>>>(agg, W1, b1, bufA, N_NODES, 16, 64, 1);
    // layer 2: agg(bufA:64) -> gemm 64x128
    aggregate_kernel<64><<<warpNodeBlocks, TPB>>>(bufA, agg, 1);
    gemm_bias_relu_kernel<<<g2, 256>>>(agg, W2, b2, bufB, N_NODES, 64, 128, 1);
    // layer 3: agg(bufB:128) -> gemm 128x256
    aggregate_kernel<128><<<warpNodeBlocks, TPB>>>(bufB, agg, 1);
    gemm_bias_relu_kernel<<<g3, 256>>>(agg, W3, b3, bufA, N_NODES, 128, 256, 1);
    // layer 4: agg(bufA:256) -> gemm 256x512
    aggregate_kernel<256><<<warpNodeBlocks, TPB>>>(bufA, agg, 1);
    gemm_bias_relu_kernel<<<g4, 256>>>(agg, W4, b4, bufB, N_NODES, 256, 512, 1);
    // layer 5: gemm 512x1 (rowdot) -> add-aggregate -> sigmoid
    rowdot_kernel<<<warpNodeBlocks, TPB>>>(bufB, W5, hbuf);
    final_agg_kernel<<<nodeBlocks, TPB>>>(hbuf, b5, out);
}

// round 2
// speedup vs baseline: 1.7573x; 1.7573x over previous
#include <cuda_runtime.h>
#include <math.h>
#include <stdint.h>

#define N_NODES 20000
#define N_EDGES 320000
#define NBLK    ((N_NODES + 255) / 256)   // 79

// ---------------- device scratch (static, allocation-free) ----------------
__device__ int   g_e64;
__device__ int   g_cnt[N_NODES];
__device__ int   g_ptr[N_NODES + 1];
__device__ int   g_cur[N_NODES];
__device__ int   g_src[N_EDGES];
__device__ int   g_bsum[NBLK + 1];
__device__ int   g_boff[NBLK + 1];
__device__ float g_deg[N_NODES];
__device__ float g_dinv[N_NODES];
__device__ float g_agg[N_NODES * 256];
__device__ float g_bufA[N_NODES * 256];
__device__ float g_bufB[N_NODES * 512];
__device__ float g_h[N_NODES];

// ---------------- edge access (int32 / int64 agnostic) ----------------
__device__ __forceinline__ int edge_at(const void* e, long long idx) {
    if (g_e64) return (int)((const long long*)e)[idx];
    return ((const int*)e)[idx];
}

__global__ void detect_dtype_kernel(const void* e) {
    const long long* p = (const long long*)e;
    bool ok = true;
#pragma unroll
    for (int i = 0; i < 8; i++) {
        long long v = p[i];
        if (v < 0 || v >= N_NODES) ok = false;
    }
    g_e64 = ok ? 1 : 0;
}

__global__ void init_cnt_kernel() {
    int i = blockIdx.x * blockDim.x + threadIdx.x;
    if (i < N_NODES) g_cnt[i] = 0;
}

__global__ void histo_kernel(const void* e) {
    int i = blockIdx.x * blockDim.x + threadIdx.x;
    if (i < N_EDGES) {
        int dst = edge_at(e, (long long)N_EDGES + i);
        atomicAdd(&g_cnt[dst], 1);
    }
}

// -------- hierarchical scan: per-block inclusive -> scan block sums -> add --------
__global__ void partial_scan_kernel() {
    __shared__ int sh[256];
    int b = blockIdx.x, t = threadIdx.x;
    int i = b * 256 + t;
    sh[t] = (i < N_NODES) ? g_cnt[i] : 0;
    __syncthreads();
#pragma unroll
    for (int off = 1; off < 256; off <<= 1) {
        int add = (t >= off) ? sh[t - off] : 0;
        __syncthreads();
        sh[t] += add;
        __syncthreads();
    }
    if (i < N_NODES) g_ptr[i + 1] = sh[t];
    if (t == 255) g_bsum[b] = sh[255];
}

__global__ void scan_bsum_kernel() {
    __shared__ int sh[128];
    int t = threadIdx.x;
    sh[t] = (t < NBLK) ? g_bsum[t] : 0;
    __syncthreads();
#pragma unroll
    for (int off = 1; off < 128; off <<= 1) {
        int add = (t >= off) ? sh[t - off] : 0;
        __syncthreads();
        sh[t] += add;
        __syncthreads();
    }
    if (t < NBLK) g_boff[t] = (t == 0) ? 0 : sh[t - 1];
}

__global__ void add_off_kernel() {
    int i = blockIdx.x * blockDim.x + threadIdx.x;
    if (i == 0) g_ptr[0] = 0;
    if (i < N_NODES) g_ptr[i + 1] += g_boff[i >> 8];
}

__global__ void node_init_kernel() {
    int i = blockIdx.x * blockDim.x + threadIdx.x;
    if (i < N_NODES) {
        float d = (float)(g_cnt[i] + 1);
        g_deg[i]  = d;
        g_dinv[i] = rsqrtf(d);
        g_cur[i]  = g_ptr[i];
    }
}

__global__ void fill_kernel(const void* e) {
    int i = blockIdx.x * blockDim.x + threadIdx.x;
    if (i < N_EDGES) {
        int src = edge_at(e, i);
        int dst = edge_at(e, (long long)N_EDGES + i);
        int pos = atomicAdd(&g_cur[dst], 1);
        g_src[pos] = src;
    }
}

// ---------------- aggregation: one warp per node ----------------
template <int D>
__global__ void aggregate_kernel(const float* __restrict__ X, float* __restrict__ A,
                                 int mean_aggr) {
    int gtid = blockIdx.x * blockDim.x + threadIdx.x;
    int node = gtid >> 5;
    int lane = threadIdx.x & 31;
    if (node >= N_NODES) return;
    constexpr int R = (D + 31) / 32;
    float acc[R];
#pragma unroll
    for (int r = 0; r < R; r++) acc[r] = 0.f;
    int beg = g_ptr[node], end = g_ptr[node + 1];
    for (int p = beg; p < end; p++) {
        int s = g_src[p];
        float w = g_dinv[s];
        const float* xs = X + (long long)s * D;
#pragma unroll
        for (int r = 0; r < R; r++) {
            int dim = lane + 32 * r;
            if (dim < D) acc[r] += w * xs[dim];
        }
    }
    float di = g_dinv[node];
    float selfw = di * di;
    float scale = mean_aggr ? (1.0f / g_deg[node]) : 1.0f;
    const float* xi = X + (long long)node * D;
    float* ao = A + (long long)node * D;
#pragma unroll
    for (int r = 0; r < R; r++) {
        int dim = lane + 32 * r;
        if (dim < D) ao[dim] = (di * acc[r] + selfw * xi[dim]) * scale;
    }
}

// ---------------- tf32 tensor-core GEMM ----------------
__device__ __forceinline__ uint32_t f2tf32(float f) {
    uint32_t r;
    asm("cvt.rna.tf32.f32 %0, %1;" : "=r"(r) : "f"(f));
    return r;
}

__device__ __forceinline__ void mma_tf32(float& c0, float& c1, float& c2, float& c3,
                                         uint32_t a0, uint32_t a1, uint32_t a2, uint32_t a3,
                                         uint32_t b0, uint32_t b1) {
    asm volatile(
        "mma.sync.aligned.m16n8k8.row.col.f32.tf32.tf32.f32 "
        "{%0,%1,%2,%3},{%4,%5,%6,%7},{%8,%9},{%0,%1,%2,%3};\n"
        : "+f"(c0), "+f"(c1), "+f"(c2), "+f"(c3)
        : "r"(a0), "r"(a1), "r"(a2), "r"(a3), "r"(b0), "r"(b1));
}

// C[M,N] = act(A[M,K] @ B[K,N] + bias). BM=128, BK=32, BN template (64 or 128).
template <int BN>
__global__ __launch_bounds__(256)
void gemm_tf32_kernel(const float* __restrict__ A, const float* __restrict__ B,
                      const float* __restrict__ bias, float* __restrict__ C,
                      int M, int K, int N, int do_relu) {
    constexpr int BM = 128, BK = 32;
    constexpr int ASTR = BK + 4;     // bank-conflict-free A stride
    constexpr int BSTR = BN + 8;     // bank-conflict-free B stride
    constexpr int WN = BN / 64;      // warps along N
    constexpr int WM = 8 / WN;       // warps along M
    constexpr int MT = BM / WM / 16; // 16-row m-tiles per warp

    __shared__ uint32_t As[BM][ASTR];
    __shared__ uint32_t Bs[BK][BSTR];

    int tid  = threadIdx.x;
    int lane = tid & 31;
    int warp = tid >> 5;
    int warp_m = warp % WM, warp_n = warp / WM;
    int row0 = warp_m * (MT * 16);
    int col0 = warp_n * 64;
    int rowBase = blockIdx.y * BM;
    int colBase = blockIdx.x * BN;

    float acc[MT][8][4];
#pragma unroll
    for (int mt = 0; mt < MT; mt++)
#pragma unroll
        for (int nt = 0; nt < 8; nt++)
#pragma unroll
            for (int q = 0; q < 4; q++) acc[mt][nt][q] = 0.f;

    int lr = lane >> 2;   // lane/4
    int lc = lane & 3;    // lane%4

    for (int k0 = 0; k0 < K; k0 += BK) {
        // load A tile (BM x BK), coalesced: 32 consecutive tids cover one row
#pragma unroll
        for (int i = 0; i < (BM * BK) / 256; i++) {
            int idx = tid + i * 256;
            int r = idx >> 5, c = idx & 31;
            int gr = rowBase + r, gk = k0 + c;
            float v = (gr < M && gk < K) ? A[(long long)gr * K + gk] : 0.f;
            As[r][c] = f2tf32(v);
        }
        // load B tile (BK x BN)
#pragma unroll
        for (int i = 0; i < (BK * BN) / 256; i++) {
            int idx = tid + i * 256;
            int r = idx / BN, c = idx % BN;
            int gk = k0 + r;
            float v = (gk < K) ? B[(long long)gk * N + colBase + c] : 0.f;
            Bs[r][c] = f2tf32(v);
        }
        __syncthreads();

#pragma unroll
        for (int ks = 0; ks < BK / 8; ks++) {
            int k8 = ks * 8;
            uint32_t b0[8], b1[8];
#pragma unroll
            for (int nt = 0; nt < 8; nt++) {
                int n = col0 + nt * 8 + lr;
                b0[nt] = Bs[k8 + lc][n];
                b1[nt] = Bs[k8 + 4 + lc][n];
            }
#pragma unroll
            for (int mt = 0; mt < MT; mt++) {
                int r = row0 + mt * 16 + lr;
                uint32_t a0 = As[r][k8 + lc];
                uint32_t a1 = As[r + 8][k8 + lc];
                uint32_t a2 = As[r][k8 + 4 + lc];
                uint32_t a3 = As[r + 8][k8 + 4 + lc];
#pragma unroll
                for (int nt = 0; nt < 8; nt++)
                    mma_tf32(acc[mt][nt][0], acc[mt][nt][1], acc[mt][nt][2], acc[mt][nt][3],
                             a0, a1, a2, a3, b0[nt], b1[nt]);
            }
        }
        __syncthreads();
    }

    // epilogue: c0/c1 at (row, 2*lc + {0,1}), c2/c3 at (row+8, ...)
#pragma unroll
    for (int mt = 0; mt < MT; mt++) {
#pragma unroll
        for (int nt = 0; nt < 8; nt++) {
            int c = colBase + col0 + nt * 8 + lc * 2;
            float bv0 = bias[c], bv1 = bias[c + 1];
            int r1 = rowBase + row0 + mt * 16 + lr;
            int r2 = r1 + 8;
            float v0 = acc[mt][nt][0] + bv0, v1 = acc[mt][nt][1] + bv1;
            float v2 = acc[mt][nt][2] + bv0, v3 = acc[mt][nt][3] + bv1;
            if (do_relu) {
                v0 = fmaxf(v0, 0.f); v1 = fmaxf(v1, 0.f);
                v2 = fmaxf(v2, 0.f); v3 = fmaxf(v3, 0.f);
            }
            if (r1 < M) {
                C[(long long)r1 * N + c]     = v0;
                C[(long long)r1 * N + c + 1] = v1;
            }
            if (r2 < M) {
                C[(long long)r2 * N + c]     = v2;
                C[(long long)r2 * N + c + 1] = v3;
            }
        }
    }
}

// ---------------- layer 5: h[i] = X[i,:] . W5  (K=512) ----------------
__global__ void rowdot_kernel(const float* __restrict__ X, const float* __restrict__ W,
                              float* __restrict__ h) {
    int gtid = blockIdx.x * blockDim.x + threadIdx.x;
    int row = gtid >> 5;
    int lane = threadIdx.x & 31;
    if (row >= N_NODES) return;
    const float* xr = X + (long long)row * 512;
    float s = 0.f;
#pragma unroll
    for (int k = lane; k < 512; k += 32) s += xr[k] * W[k];
#pragma unroll
    for (int off = 16; off > 0; off >>= 1) s += __shfl_down_sync(0xffffffff, s, off);
    if (lane == 0) h[row] = s;
}

__global__ void final_agg_kernel(const float* __restrict__ h, const float* __restrict__ b5,
                                 float* __restrict__ out) {
    int i = blockIdx.x * blockDim.x + threadIdx.x;
    if (i >= N_NODES) return;
    float s = 0.f;
    int beg = g_ptr[i], end = g_ptr[i + 1];
    for (int p = beg; p < end; p++) {
        int src = g_src[p];
        s += g_dinv[src] * h[src];
    }
    float di = g_dinv[i];
    float v = di * s + di * di * h[i] + b5[0];
    out[i] = 1.f / (1.f + expf(-v));
}

// ---------------- launch ----------------
extern "C" void kernel_launch(void* const* d_in, const int* in_sizes, int n_in,
                              void* d_out, int out_size) {
    const float* x  = (const float*)d_in[0];
    const void*  ei = d_in[1];
    const float* W1 = (const float*)d_in[2],  *b1 = (const float*)d_in[3];
    const float* W2 = (const float*)d_in[4],  *b2 = (const float*)d_in[5];
    const float* W3 = (const float*)d_in[6],  *b3 = (const float*)d_in[7];
    const float* W4 = (const float*)d_in[8],  *b4 = (const float*)d_in[9];
    const float* W5 = (const float*)d_in[10], *b5 = (const float*)d_in[11];
    float* out = (float*)d_out;

    float *agg, *bufA, *bufB, *hbuf;
    cudaGetSymbolAddress((void**)&agg,  g_agg);
    cudaGetSymbolAddress((void**)&bufA, g_bufA);
    cudaGetSymbolAddress((void**)&bufB, g_bufB);
    cudaGetSymbolAddress((void**)&hbuf, g_h);

    const int TPB = 256;
    int nodeBlocks = (N_NODES + TPB - 1) / TPB;
    int edgeBlocks = (N_EDGES + TPB - 1) / TPB;
    int warpNodeBlocks = (N_NODES * 32 + TPB - 1) / TPB;

    // --- preprocessing ---
    detect_dtype_kernel<<<1, 1>>>(ei);
    init_cnt_kernel<<<nodeBlocks, TPB>>>();
    histo_kernel<<<edgeBlocks, TPB>>>(ei);
    partial_scan_kernel<<<NBLK, 256>>>();
    scan_bsum_kernel<<<1, 128>>>();
    add_off_kernel<<<nodeBlocks, TPB>>>();
    node_init_kernel<<<nodeBlocks, TPB>>>();
    fill_kernel<<<edgeBlocks, TPB>>>(ei);

    int mBlocks = (N_NODES + 127) / 128;
    dim3 g1(64 / 64,   mBlocks);
    dim3 g2(128 / 128, mBlocks);
    dim3 g3(256 / 128, mBlocks);
    dim3 g4(512 / 128, mBlocks);

    aggregate_kernel<16><<<warpNodeBlocks, TPB>>>(x, agg, 1);
    gemm_tf32_kernel<64><<<g1, 256>>>(agg, W1, b1, bufA, N_NODES, 16, 64, 1);
    aggregate_kernel<64><<<warpNodeBlocks, TPB>>>(bufA, agg, 1);
    gemm_tf32_kernel<128><<<g2, 256>>>(agg, W2, b2, bufB, N_NODES, 64, 128, 1);
    aggregate_kernel<128><<<warpNodeBlocks, TPB>>>(bufB, agg, 1);
    gemm_tf32_kernel<128><<<g3, 256>>>(agg, W3, b3, bufA, N_NODES, 128, 256, 1);
    aggregate_kernel<256><<<warpNodeBlocks, TPB>>>(bufA, agg, 1);
    gemm_tf32_kernel<128><<<g4, 256>>>(agg, W4, b4, bufB, N_NODES, 256, 512, 1);
    rowdot_kernel<<<warpNodeBlocks, TPB>>>(bufB, W5, hbuf);
    final_agg_kernel<<<nodeBlocks, TPB>>>(hbuf, b5, out);
}

// round 4
// speedup vs baseline: 2.0030x; 1.1398x over previous
#include <cuda_runtime.h>
#include <math.h>
#include <stdint.h>

#define N_NODES 20000
#define N_EDGES 320000

// ---------------- device scratch ----------------
__device__ int   g_e64;
__device__ int   g_cnt[N_NODES];
__device__ int   g_ptr[N_NODES + 1];
__device__ int   g_cur[N_NODES];
__device__ int2  g_srcw[N_EDGES];          // {src, bits(dinv[src])}
__device__ float g_deg[N_NODES];
__device__ float g_dinv[N_NODES];
__device__ float g_agg[N_NODES * 256];
__device__ float g_bufA[N_NODES * 256];    // L1 out (64) / L3 out (256)
__device__ float g_bufB[N_NODES * 128];    // L2 out (128)
__device__ float g_hpart[8 * N_NODES];     // layer-5 dot partials
__device__ float g_h[N_NODES];

__device__ __forceinline__ int edge_at(const void* e, long long idx) {
    if (g_e64) return (int)((const long long*)e)[idx];
    return ((const int*)e)[idx];
}

// ---------------- preprocessing ----------------
__global__ void init_detect_kernel(const void* e) {
    int i = blockIdx.x * blockDim.x + threadIdx.x;
    if (i < N_NODES) g_cnt[i] = 0;
    if (i == 0) {
        const long long* p = (const long long*)e;
        bool ok = true;
#pragma unroll
        for (int k = 0; k < 8; k++) {
            long long v = p[k];
            if (v < 0 || v >= N_NODES) ok = false;
        }
        g_e64 = ok ? 1 : 0;
    }
}

__global__ void histo_kernel(const void* e) {
    int i = blockIdx.x * blockDim.x + threadIdx.x;
    if (i < N_EDGES) atomicAdd(&g_cnt[edge_at(e, (long long)N_EDGES + i)], 1);
}

// single-block scan + node init (1024 threads, 20 elems/thread serial + shfl scan)
__global__ void scan_node_init_kernel() {
    const int C = (N_NODES + 1023) / 1024;   // 20
    int t = threadIdx.x;
    int base = t * C;
    int local[C];
    int sum = 0;
#pragma unroll
    for (int c = 0; c < C; c++) {
        int i = base + c;
        int v = (i < N_NODES) ? g_cnt[i] : 0;
        sum += v;
        local[c] = sum;
    }
    int lane = t & 31, wid = t >> 5;
    int incl = sum;
#pragma unroll
    for (int o = 1; o < 32; o <<= 1) {
        int y = __shfl_up_sync(0xffffffffu, incl, o);
        if (lane >= o) incl += y;
    }
    __shared__ int ws[32];
    if (lane == 31) ws[wid] = incl;
    __syncthreads();
    if (wid == 0) {
        int v = ws[lane];
        int iv = v;
#pragma unroll
        for (int o = 1; o < 32; o <<= 1) {
            int y = __shfl_up_sync(0xffffffffu, iv, o);
            if (lane >= o) iv += y;
        }
        ws[lane] = iv - v;   // exclusive
    }
    __syncthreads();
    int offset = ws[wid] + (incl - sum);
    if (t == 0) g_ptr[0] = 0;
#pragma unroll
    for (int c = 0; c < C; c++) {
        int i = base + c;
        if (i >= N_NODES) break;
        int inclv = offset + local[c];
        g_ptr[i + 1] = inclv;
        g_cur[i] = offset + (c ? local[c - 1] : 0);
        int v = local[c] - (c ? local[c - 1] : 0);
        float d = (float)(v + 1);
        g_deg[i] = d;
        g_dinv[i] = rsqrtf(d);
    }
}

__global__ void fill_kernel(const void* e) {
    int i = blockIdx.x * blockDim.x + threadIdx.x;
    if (i < N_EDGES) {
        int src = edge_at(e, i);
        int dst = edge_at(e, (long long)N_EDGES + i);
        int pos = atomicAdd(&g_cur[dst], 1);
        g_srcw[pos] = make_int2(src, __float_as_int(g_dinv[src]));
    }
}

// ---------------- aggregation (mean, symmetric norm, self-loop) ----------------
template <int D>
__global__ void aggregate_kernel(const float* __restrict__ X, float* __restrict__ A) {
    int node = (blockIdx.x * blockDim.x + threadIdx.x) >> 5;
    int lane = threadIdx.x & 31;
    if (node >= N_NODES) return;
    int beg = g_ptr[node], end = g_ptr[node + 1];
    float di = g_dinv[node];
    float selfw = di * di;
    float scale = 1.0f / g_deg[node];
    const float* xi = X + (long long)node * D;
    float* ao = A + (long long)node * D;

    if constexpr (D >= 128) {
        constexpr int R = D / 128;
        float4 acc[R];
#pragma unroll
        for (int r = 0; r < R; r++) acc[r] = make_float4(0.f, 0.f, 0.f, 0.f);
        for (int p = beg; p < end; p++) {
            int2 sw = g_srcw[p];
            float w = __int_as_float(sw.y);
            const float4* xs = (const float4*)(X + (long long)sw.x * D);
#pragma unroll
            for (int r = 0; r < R; r++) {
                float4 v = xs[lane + 32 * r];
                acc[r].x += w * v.x; acc[r].y += w * v.y;
                acc[r].z += w * v.z; acc[r].w += w * v.w;
            }
        }
        const float4* xi4 = (const float4*)xi;
        float4* ao4 = (float4*)ao;
#pragma unroll
        for (int r = 0; r < R; r++) {
            float4 s = xi4[lane + 32 * r];
            float4 o;
            o.x = (di * acc[r].x + selfw * s.x) * scale;
            o.y = (di * acc[r].y + selfw * s.y) * scale;
            o.z = (di * acc[r].z + selfw * s.z) * scale;
            o.w = (di * acc[r].w + selfw * s.w) * scale;
            ao4[lane + 32 * r] = o;
        }
    } else if constexpr (D == 64) {
        float2 acc = make_float2(0.f, 0.f);
        for (int p = beg; p < end; p++) {
            int2 sw = g_srcw[p];
            float w = __int_as_float(sw.y);
            float2 v = ((const float2*)(X + (long long)sw.x * 64))[lane];
            acc.x += w * v.x; acc.y += w * v.y;
        }
        float2 s = ((const float2*)xi)[lane];
        float2 o;
        o.x = (di * acc.x + selfw * s.x) * scale;
        o.y = (di * acc.y + selfw * s.y) * scale;
        ((float2*)ao)[lane] = o;
    } else {   // D == 16
        float acc = 0.f;
        for (int p = beg; p < end; p++) {
            int2 sw = g_srcw[p];
            float w = __int_as_float(sw.y);
            if (lane < 16) acc += w * X[(long long)sw.x * 16 + lane];
        }
        if (lane < 16) ao[lane] = (di * acc + selfw * xi[lane]) * scale;
    }
}

// ---------------- tf32 tensor-core GEMM (cp.async double-buffered) ----------------
__device__ __forceinline__ void mma_tf32(float& c0, float& c1, float& c2, float& c3,
                                         uint32_t a0, uint32_t a1, uint32_t a2, uint32_t a3,
                                         uint32_t b0, uint32_t b1) {
    asm volatile(
        "mma.sync.aligned.m16n8k8.row.col.f32.tf32.tf32.f32 "
        "{%0,%1,%2,%3},{%4,%5,%6,%7},{%8,%9},{%0,%1,%2,%3};\n"
        : "+f"(c0), "+f"(c1), "+f"(c2), "+f"(c3)
        : "r"(a0), "r"(a1), "r"(a2), "r"(a3), "r"(b0), "r"(b1));
}

__device__ __forceinline__ void cp16(uint32_t dst, const void* src, bool pred) {
    int bytes = pred ? 16 : 0;
    asm volatile("cp.async.ca.shared.global [%0], [%1], 16, %2;\n"
                 :: "r"(dst), "l"(src), "r"(bytes));
}

template <int BN, bool FUSE>
__global__ __launch_bounds__(256)
void gemm_tf32_kernel(const float* __restrict__ A, const float* __restrict__ B,
                      const float* __restrict__ bias, float* __restrict__ C,
                      const float* __restrict__ w5, float* __restrict__ hpart,
                      int M, int K, int N, int do_relu) {
    constexpr int BM = 128, BK = 16;
    constexpr int ASTR = BK + 4;
    constexpr int BSTR = BN + 8;
    constexpr int WN = BN / 64, WM = 8 / WN, MT = BM / (WM * 16);

    __shared__ float As[2][BM][ASTR];
    __shared__ float Bs[2][BK][BSTR];

    int tid = threadIdx.x, lane = tid & 31, warp = tid >> 5;
    int warp_m = warp % WM, warp_n = warp / WM;
    int row0 = warp_m * (MT * 16), col0 = warp_n * 64;
    int rowBase = blockIdx.y * BM, colBase = blockIdx.x * BN;

    int ar = tid >> 2;            // A: row within 64-row wave
    int ac = (tid & 3) * 4;       // A: float col
    int br = tid / (BN / 4);      // B: row within wave
    int bc = (tid % (BN / 4)) * 4;

    auto issue = [&](int kt, int s) {
        int k0 = kt * BK;
#pragma unroll
        for (int i = 0; i < 2; i++) {
            int r = ar + i * 64;
            int gr = rowBase + r;
            bool ok = gr < M;
            const float* src = A + (long long)(ok ? gr : 0) * K + k0 + ac;
            cp16((uint32_t)__cvta_generic_to_shared(&As[s][r][ac]), src, ok);
        }
        constexpr int RPW = 1024 / BN;
#pragma unroll
        for (int i = 0; i < BK / RPW; i++) {
            int r = br + i * RPW;
            const float* src = B + (long long)(k0 + r) * N + colBase + bc;
            cp16((uint32_t)__cvta_generic_to_shared(&Bs[s][r][bc]), src, true);
        }
        asm volatile("cp.async.commit_group;\n");
    };

    float acc[MT][8][4];
#pragma unroll
    for (int mt = 0; mt < MT; mt++)
#pragma unroll
        for (int nt = 0; nt < 8; nt++)
#pragma unroll
            for (int q = 0; q < 4; q++) acc[mt][nt][q] = 0.f;

    int lr = lane >> 2, lc = lane & 3;
    int KT = K / BK;

    issue(0, 0);
    for (int kt = 0; kt < KT; kt++) {
        int s = kt & 1;
        if (kt + 1 < KT) {
            issue(kt + 1, 1 - s);
            asm volatile("cp.async.wait_group 1;\n");
        } else {
            asm volatile("cp.async.wait_group 0;\n");
        }
        __syncthreads();
#pragma unroll
        for (int ks = 0; ks < 2; ks++) {
            int k8 = ks * 8;
            uint32_t b0[8], b1[8];
#pragma unroll
            for (int nt = 0; nt < 8; nt++) {
                int n = col0 + nt * 8 + lr;
                b0[nt] = __float_as_uint(Bs[s][k8 + lc][n]);
                b1[nt] = __float_as_uint(Bs[s][k8 + 4 + lc][n]);
            }
#pragma unroll
            for (int mt = 0; mt < MT; mt++) {
                int r = row0 + mt * 16 + lr;
                uint32_t a0 = __float_as_uint(As[s][r][k8 + lc]);
                uint32_t a1 = __float_as_uint(As[s][r + 8][k8 + lc]);
                uint32_t a2 = __float_as_uint(As[s][r][k8 + 4 + lc]);
                uint32_t a3 = __float_as_uint(As[s][r + 8][k8 + 4 + lc]);
#pragma unroll
                for (int nt = 0; nt < 8; nt++)
                    mma_tf32(acc[mt][nt][0], acc[mt][nt][1], acc[mt][nt][2], acc[mt][nt][3],
                             a0, a1, a2, a3, b0[nt], b1[nt]);
            }
        }
        __syncthreads();
    }

#pragma unroll
    for (int mt = 0; mt < MT; mt++) {
        int r1 = rowBase + row0 + mt * 16 + lr;
        int r2 = r1 + 8;
        float d1 = 0.f, d2 = 0.f;
#pragma unroll
        for (int nt = 0; nt < 8; nt++) {
            int c = colBase + col0 + nt * 8 + lc * 2;
            float bv0 = bias[c], bv1 = bias[c + 1];
            float v0 = acc[mt][nt][0] + bv0, v1 = acc[mt][nt][1] + bv1;
            float v2 = acc[mt][nt][2] + bv0, v3 = acc[mt][nt][3] + bv1;
            if (do_relu) {
                v0 = fmaxf(v0, 0.f); v1 = fmaxf(v1, 0.f);
                v2 = fmaxf(v2, 0.f); v3 = fmaxf(v3, 0.f);
            }
            if (FUSE) {
                float w0 = w5[c], w1 = w5[c + 1];
                if (r1 < M) d1 += v0 * w0 + v1 * w1;
                if (r2 < M) d2 += v2 * w0 + v3 * w1;
            } else {
                if (r1 < M) {
                    C[(long long)r1 * N + c]     = v0;
                    C[(long long)r1 * N + c + 1] = v1;
                }
                if (r2 < M) {
                    C[(long long)r2 * N + c]     = v2;
                    C[(long long)r2 * N + c + 1] = v3;
                }
            }
        }
        if (FUSE) {
            d1 += __shfl_xor_sync(0xffffffffu, d1, 1);
            d1 += __shfl_xor_sync(0xffffffffu, d1, 2);
            d2 += __shfl_xor_sync(0xffffffffu, d2, 1);
            d2 += __shfl_xor_sync(0xffffffffu, d2, 2);
            int slot = blockIdx.x * WN + warp_n;
            if (lc == 0) {
                if (r1 < M) hpart[slot * N_NODES + r1] = d1;
                if (r2 < M) hpart[slot * N_NODES + r2] = d2;
            }
        }
    }
}

// ---------------- layer-5 partial reduce + add-aggregate + sigmoid ----------------
__global__ void hreduce_kernel(const float* __restrict__ hpart, float* __restrict__ h) {
    int i = blockIdx.x * blockDim.x + threadIdx.x;
    if (i < N_NODES) {
        float s = 0.f;
#pragma unroll
        for (int j = 0; j < 8; j++) s += hpart[j * N_NODES + i];
        h[i] = s;
    }
}

__global__ void final_agg_kernel(const float* __restrict__ h, const float* __restrict__ b5,
                                 float* __restrict__ out) {
    int i = blockIdx.x * blockDim.x + threadIdx.x;
    if (i >= N_NODES) return;
    float s = 0.f;
    int beg = g_ptr[i], end = g_ptr[i + 1];
    for (int p = beg; p < end; p++) {
        int2 sw = g_srcw[p];
        s += __int_as_float(sw.y) * h[sw.x];
    }
    float di = g_dinv[i];
    float v = di * s + di * di * h[i] + b5[0];
    out[i] = 1.f / (1.f + expf(-v));
}

// ---------------- launch ----------------
extern "C" void kernel_launch(void* const* d_in, const int* in_sizes, int n_in,
                              void* d_out, int out_size) {
    const float* x  = (const float*)d_in[0];
    const void*  ei = d_in[1];
    const float* W1 = (const float*)d_in[2],  *b1 = (const float*)d_in[3];
    const float* W2 = (const float*)d_in[4],  *b2 = (const float*)d_in[5];
    const float* W3 = (const float*)d_in[6],  *b3 = (const float*)d_in[7];
    const float* W4 = (const float*)d_in[8],  *b4 = (const float*)d_in[9];
    const float* W5 = (const float*)d_in[10], *b5 = (const float*)d_in[11];
    float* out = (float*)d_out;

    float *agg, *bufA, *bufB, *hpart, *hbuf;
    cudaGetSymbolAddress((void**)&agg,   g_agg);
    cudaGetSymbolAddress((void**)&bufA,  g_bufA);
    cudaGetSymbolAddress((void**)&bufB,  g_bufB);
    cudaGetSymbolAddress((void**)&hpart, g_hpart);
    cudaGetSymbolAddress((void**)&hbuf,  g_h);

    const int TPB = 256;
    int nodeBlocks = (N_NODES + TPB - 1) / TPB;
    int edgeBlocks = (N_EDGES + TPB - 1) / TPB;
    int warpNodeBlocks = (N_NODES * 32 + TPB - 1) / TPB;
    int mBlocks = (N_NODES + 127) / 128;

    init_detect_kernel<<<nodeBlocks, TPB>>>(ei);
    histo_kernel<<<edgeBlocks, TPB>>>(ei);
    scan_node_init_kernel<<<1, 1024>>>();
    fill_kernel<<<edgeBlocks, TPB>>>(ei);

    aggregate_kernel<16><<<warpNodeBlocks, TPB>>>(x, agg);
    gemm_tf32_kernel<64, false><<<dim3(1, mBlocks), 256>>>(agg, W1, b1, bufA, nullptr, nullptr,
                                                           N_NODES, 16, 64, 1);
    aggregate_kernel<64><<<warpNodeBlocks, TPB>>>(bufA, agg);
    gemm_tf32_kernel<128, false><<<dim3(1, mBlocks), 256>>>(agg, W2, b2, bufB, nullptr, nullptr,
                                                            N_NODES, 64, 128, 1);
    aggregate_kernel<128><<<warpNodeBlocks, TPB>>>(bufB, agg);
    gemm_tf32_kernel<128, false><<<dim3(2, mBlocks), 256>>>(agg, W3, b3, bufA, nullptr, nullptr,
                                                            N_NODES, 128, 256, 1);
    aggregate_kernel<256><<<warpNodeBlocks, TPB>>>(bufA, agg);
    gemm_tf32_kernel<128, true><<<dim3(4, mBlocks), 256>>>(agg, W4, b4, nullptr, W5, hpart,
                                                           N_NODES, 256, 512, 1);
    hreduce_kernel<<<nodeBlocks, TPB>>>(hpart, hbuf);
    final_agg_kernel<<<nodeBlocks, TPB>>>(hbuf, b5, out);
}

// round 5
// speedup vs baseline: 2.1690x; 1.0829x over previous
#include <cuda_runtime.h>
#include <cuda_fp16.h>
#include <math.h>
#include <stdint.h>

#define N_NODES 20000
#define N_EDGES 320000

// ---------------- device scratch ----------------
__device__ int   g_e64;
__device__ int   g_cnt[N_NODES];
__device__ int   g_ptr[N_NODES + 1];
__device__ int   g_cur[N_NODES];
__device__ __align__(16) int2  g_srcw[N_EDGES];
__device__ float g_deg[N_NODES];
__device__ float g_dinv[N_NODES];
__device__ __align__(256) float  g_agg[N_NODES * 256];      // GEMM A input (fp32)
__device__ __align__(256) __half g_featA[N_NODES * 256];    // L1 out (64) / L3 out (256), fp16
__device__ __align__(256) __half g_featB[N_NODES * 128];    // L2 out (128), fp16
__device__ float g_hpart[8 * N_NODES];
__device__ float g_h[N_NODES];

__device__ __forceinline__ int edge_at(const void* e, long long idx) {
    if (g_e64) return (int)((const long long*)e)[idx];
    return ((const int*)e)[idx];
}

// ---------------- preprocessing ----------------
__global__ void init_detect_kernel(const void* e) {
    int i = blockIdx.x * blockDim.x + threadIdx.x;
    if (i < N_NODES) g_cnt[i] = 0;
    if (i == 0) {
        const long long* p = (const long long*)e;
        bool ok = true;
#pragma unroll
        for (int k = 0; k < 8; k++) {
            long long v = p[k];
            if (v < 0 || v >= N_NODES) ok = false;
        }
        g_e64 = ok ? 1 : 0;
    }
}

__global__ void histo_kernel(const void* e) {
    int i0 = (blockIdx.x * blockDim.x + threadIdx.x) * 4;
#pragma unroll
    for (int j = 0; j < 4; j++) {
        int i = i0 + j;
        if (i < N_EDGES) atomicAdd(&g_cnt[edge_at(e, (long long)N_EDGES + i)], 1);
    }
}

__global__ void scan_node_init_kernel() {
    const int C = (N_NODES + 1023) / 1024;   // 20
    int t = threadIdx.x;
    int base = t * C;
    int local[C];
    int sum = 0;
#pragma unroll
    for (int c = 0; c < C; c++) {
        int i = base + c;
        int v = (i < N_NODES) ? g_cnt[i] : 0;
        sum += v;
        local[c] = sum;
    }
    int lane = t & 31, wid = t >> 5;
    int incl = sum;
#pragma unroll
    for (int o = 1; o < 32; o <<= 1) {
        int y = __shfl_up_sync(0xffffffffu, incl, o);
        if (lane >= o) incl += y;
    }
    __shared__ int ws[32];
    if (lane == 31) ws[wid] = incl;
    __syncthreads();
    if (wid == 0) {
        int v = ws[lane];
        int iv = v;
#pragma unroll
        for (int o = 1; o < 32; o <<= 1) {
            int y = __shfl_up_sync(0xffffffffu, iv, o);
            if (lane >= o) iv += y;
        }
        ws[lane] = iv - v;
    }
    __syncthreads();
    int offset = ws[wid] + (incl - sum);
    if (t == 0) g_ptr[0] = 0;
#pragma unroll
    for (int c = 0; c < C; c++) {
        int i = base + c;
        if (i >= N_NODES) break;
        g_ptr[i + 1] = offset + local[c];
        g_cur[i] = offset + (c ? local[c - 1] : 0);
        int v = local[c] - (c ? local[c - 1] : 0);
        float d = (float)(v + 1);
        g_deg[i] = d;
        g_dinv[i] = rsqrtf(d);
    }
}

__global__ void fill_kernel(const void* e) {
    int i0 = (blockIdx.x * blockDim.x + threadIdx.x) * 4;
    int src[4], pos[4];
#pragma unroll
    for (int j = 0; j < 4; j++) {
        int i = i0 + j;
        if (i < N_EDGES) {
            src[j] = edge_at(e, i);
            int dst = edge_at(e, (long long)N_EDGES + i);
            pos[j] = atomicAdd(&g_cur[dst], 1);
        }
    }
#pragma unroll
    for (int j = 0; j < 4; j++) {
        int i = i0 + j;
        if (i < N_EDGES)
            g_srcw[pos[j]] = make_int2(src[j], __float_as_int(g_dinv[src[j]]));
    }
}

// ---------------- aggregation from fp16 features (mean, sym norm, self loop) ----------------
// Lane-contiguous layout: lane owns columns [lane*V, lane*V + V), V = D/32.
template <int D>
__global__ void aggregate_half_kernel(const __half* __restrict__ X, float* __restrict__ A) {
    int node = (blockIdx.x * blockDim.x + threadIdx.x) >> 5;
    int lane = threadIdx.x & 31;
    if (node >= N_NODES) return;
    int beg = g_ptr[node], end = g_ptr[node + 1];
    float di = g_dinv[node];
    float selfw = di * di;
    float scale = 1.0f / g_deg[node];
    constexpr int V2 = D / 64;   // half2 per lane

    float2 acc[V2];
#pragma unroll
    for (int r = 0; r < V2; r++) acc[r] = make_float2(0.f, 0.f);

    for (int p = beg; p < end; p++) {
        int2 sw = g_srcw[p];
        float w = __int_as_float(sw.y);
        const __half2* xs = (const __half2*)(X + (long long)sw.x * D) + lane * V2;
        if constexpr (V2 == 4) {
            uint4 raw = *(const uint4*)xs;
            const __half2* hp = (const __half2*)&raw;
#pragma unroll
            for (int r = 0; r < 4; r++) {
                float2 v = __half22float2(hp[r]);
                acc[r].x += w * v.x; acc[r].y += w * v.y;
            }
        } else if constexpr (V2 == 2) {
            uint2 raw = *(const uint2*)xs;
            const __half2* hp = (const __half2*)&raw;
#pragma unroll
            for (int r = 0; r < 2; r++) {
                float2 v = __half22float2(hp[r]);
                acc[r].x += w * v.x; acc[r].y += w * v.y;
            }
        } else {
            float2 v = __half22float2(*xs);
            acc[0].x += w * v.x; acc[0].y += w * v.y;
        }
    }
    const __half2* xi = (const __half2*)(X + (long long)node * D) + lane * V2;
    float* ao = A + (long long)node * D + lane * (2 * V2);
#pragma unroll
    for (int r = 0; r < V2; r++) {
        float2 s = __half22float2(xi[r]);
        ao[2 * r]     = (di * acc[r].x + selfw * s.x) * scale;
        ao[2 * r + 1] = (di * acc[r].y + selfw * s.y) * scale;
    }
}

// layer-1 input aggregation (fp32 x, D=16): half-warp per node
__global__ void aggregate16_kernel(const float* __restrict__ X, float* __restrict__ A) {
    int gtid = blockIdx.x * blockDim.x + threadIdx.x;
    int node = gtid >> 4;
    int lane = threadIdx.x & 15;
    if (node >= N_NODES) return;
    int beg = g_ptr[node], end = g_ptr[node + 1];
    float di = g_dinv[node];
    float acc = 0.f;
    for (int p = beg; p < end; p++) {
        int2 sw = g_srcw[p];
        acc += __int_as_float(sw.y) * X[(long long)sw.x * 16 + lane];
    }
    float scale = 1.0f / g_deg[node];
    A[(long long)node * 16 + lane] =
        (di * acc + di * di * X[(long long)node * 16 + lane]) * scale;
}

// ---------------- tf32 tensor-core GEMM (cp.async double-buffered) ----------------
__device__ __forceinline__ void mma_tf32(float& c0, float& c1, float& c2, float& c3,
                                         uint32_t a0, uint32_t a1, uint32_t a2, uint32_t a3,
                                         uint32_t b0, uint32_t b1) {
    asm volatile(
        "mma.sync.aligned.m16n8k8.row.col.f32.tf32.tf32.f32 "
        "{%0,%1,%2,%3},{%4,%5,%6,%7},{%8,%9},{%0,%1,%2,%3};\n"
        : "+f"(c0), "+f"(c1), "+f"(c2), "+f"(c3)
        : "r"(a0), "r"(a1), "r"(a2), "r"(a3), "r"(b0), "r"(b1));
}

__device__ __forceinline__ void cp16(uint32_t dst, const void* src, bool pred) {
    int bytes = pred ? 16 : 0;
    asm volatile("cp.async.ca.shared.global [%0], [%1], 16, %2;\n"
                 :: "r"(dst), "l"(src), "r"(bytes));
}

// MODE: 0 = fp32 C, 1 = fp16 C, 2 = fused rowdot (no C)
template <int BN, int MODE>
__global__ __launch_bounds__(256)
void gemm_tf32_kernel(const float* __restrict__ A, const float* __restrict__ B,
                      const float* __restrict__ bias, __half* __restrict__ Ch,
                      const float* __restrict__ w5, float* __restrict__ hpart,
                      int M, int K, int N, int do_relu) {
    constexpr int BM = 128, BK = 16;
    constexpr int ASTR = BK + 4;
    constexpr int BSTR = BN + 8;
    constexpr int WN = BN / 64, WM = 8 / WN, MT = BM / (WM * 16);

    __shared__ float As[2][BM][ASTR];
    __shared__ float Bs[2][BK][BSTR];

    int tid = threadIdx.x, lane = tid & 31, warp = tid >> 5;
    int warp_m = warp % WM, warp_n = warp / WM;
    int row0 = warp_m * (MT * 16), col0 = warp_n * 64;
    int rowBase = blockIdx.y * BM, colBase = blockIdx.x * BN;

    int ar = tid >> 2;
    int ac = (tid & 3) * 4;
    int br = tid / (BN / 4);
    int bc = (tid % (BN / 4)) * 4;

    auto issue = [&](int kt, int s) {
        int k0 = kt * BK;
#pragma unroll
        for (int i = 0; i < 2; i++) {
            int r = ar + i * 64;
            int gr = rowBase + r;
            bool ok = gr < M;
            const float* src = A + (long long)(ok ? gr : 0) * K + k0 + ac;
            cp16((uint32_t)__cvta_generic_to_shared(&As[s][r][ac]), src, ok);
        }
        constexpr int RPW = 1024 / BN;
#pragma unroll
        for (int i = 0; i < BK / RPW; i++) {
            int r = br + i * RPW;
            const float* src = B + (long long)(k0 + r) * N + colBase + bc;
            cp16((uint32_t)__cvta_generic_to_shared(&Bs[s][r][bc]), src, true);
        }
        asm volatile("cp.async.commit_group;\n");
    };

    float acc[MT][8][4];
#pragma unroll
    for (int mt = 0; mt < MT; mt++)
#pragma unroll
        for (int nt = 0; nt < 8; nt++)
#pragma unroll
            for (int q = 0; q < 4; q++) acc[mt][nt][q] = 0.f;

    int lr = lane >> 2, lc = lane & 3;
    int KT = K / BK;

    issue(0, 0);
    for (int kt = 0; kt < KT; kt++) {
        int s = kt & 1;
        if (kt + 1 < KT) {
            issue(kt + 1, 1 - s);
            asm volatile("cp.async.wait_group 1;\n");
        } else {
            asm volatile("cp.async.wait_group 0;\n");
        }
        __syncthreads();
#pragma unroll
        for (int ks = 0; ks < 2; ks++) {
            int k8 = ks * 8;
            uint32_t b0[8], b1[8];
#pragma unroll
            for (int nt = 0; nt < 8; nt++) {
                int n = col0 + nt * 8 + lr;
                b0[nt] = __float_as_uint(Bs[s][k8 + lc][n]);
                b1[nt] = __float_as_uint(Bs[s][k8 + 4 + lc][n]);
            }
#pragma unroll
            for (int mt = 0; mt < MT; mt++) {
                int r = row0 + mt * 16 + lr;
                uint32_t a0 = __float_as_uint(As[s][r][k8 + lc]);
                uint32_t a1 = __float_as_uint(As[s][r + 8][k8 + lc]);
                uint32_t a2 = __float_as_uint(As[s][r][k8 + 4 + lc]);
                uint32_t a3 = __float_as_uint(As[s][r + 8][k8 + 4 + lc]);
#pragma unroll
                for (int nt = 0; nt < 8; nt++)
                    mma_tf32(acc[mt][nt][0], acc[mt][nt][1], acc[mt][nt][2], acc[mt][nt][3],
                             a0, a1, a2, a3, b0[nt], b1[nt]);
            }
        }
        __syncthreads();
    }

#pragma unroll
    for (int mt = 0; mt < MT; mt++) {
        int r1 = rowBase + row0 + mt * 16 + lr;
        int r2 = r1 + 8;
        float d1 = 0.f, d2 = 0.f;
#pragma unroll
        for (int nt = 0; nt < 8; nt++) {
            int c = colBase + col0 + nt * 8 + lc * 2;
            float bv0 = bias[c], bv1 = bias[c + 1];
            float v0 = acc[mt][nt][0] + bv0, v1 = acc[mt][nt][1] + bv1;
            float v2 = acc[mt][nt][2] + bv0, v3 = acc[mt][nt][3] + bv1;
            if (do_relu) {
                v0 = fmaxf(v0, 0.f); v1 = fmaxf(v1, 0.f);
                v2 = fmaxf(v2, 0.f); v3 = fmaxf(v3, 0.f);
            }
            if constexpr (MODE == 2) {
                float w0 = w5[c], w1 = w5[c + 1];
                if (r1 < M) d1 += v0 * w0 + v1 * w1;
                if (r2 < M) d2 += v2 * w0 + v3 * w1;
            } else if constexpr (MODE == 1) {
                if (r1 < M) *(__half2*)(Ch + (long long)r1 * N + c) = __floats2half2_rn(v0, v1);
                if (r2 < M) *(__half2*)(Ch + (long long)r2 * N + c) = __floats2half2_rn(v2, v3);
            }
        }
        if constexpr (MODE == 2) {
            d1 += __shfl_xor_sync(0xffffffffu, d1, 1);
            d1 += __shfl_xor_sync(0xffffffffu, d1, 2);
            d2 += __shfl_xor_sync(0xffffffffu, d2, 1);
            d2 += __shfl_xor_sync(0xffffffffu, d2, 2);
            int slot = blockIdx.x * WN + warp_n;
            if (lc == 0) {
                if (r1 < M) hpart[slot * N_NODES + r1] = d1;
                if (r2 < M) hpart[slot * N_NODES + r2] = d2;
            }
        }
    }
}

// ---------------- layer-5 reduce + add-aggregate + sigmoid ----------------
__global__ void hreduce_kernel(const float* __restrict__ hpart, float* __restrict__ h) {
    int i = blockIdx.x * blockDim.x + threadIdx.x;
    if (i < N_NODES) {
        float s = 0.f;
#pragma unroll
        for (int j = 0; j < 8; j++) s += hpart[j * N_NODES + i];
        h[i] = s;
    }
}

__global__ void final_agg_kernel(const float* __restrict__ h, const float* __restrict__ b5,
                                 float* __restrict__ out) {
    int i = blockIdx.x * blockDim.x + threadIdx.x;
    if (i >= N_NODES) return;
    float s = 0.f;
    int beg = g_ptr[i], end = g_ptr[i + 1];
    for (int p = beg; p < end; p++) {
        int2 sw = g_srcw[p];
        s += __int_as_float(sw.y) * h[sw.x];
    }
    float di = g_dinv[i];
    float v = di * s + di * di * h[i] + b5[0];
    out[i] = 1.f / (1.f + expf(-v));
}

// ---------------- launch ----------------
extern "C" void kernel_launch(void* const* d_in, const int* in_sizes, int n_in,
                              void* d_out, int out_size) {
    const float* x  = (const float*)d_in[0];
    const void*  ei = d_in[1];
    const float* W1 = (const float*)d_in[2],  *b1 = (const float*)d_in[3];
    const float* W2 = (const float*)d_in[4],  *b2 = (const float*)d_in[5];
    const float* W3 = (const float*)d_in[6],  *b3 = (const float*)d_in[7];
    const float* W4 = (const float*)d_in[8],  *b4 = (const float*)d_in[9];
    const float* W5 = (const float*)d_in[10], *b5 = (const float*)d_in[11];
    float* out = (float*)d_out;

    float *agg, *hpart, *hbuf;
    __half *featA, *featB;
    cudaGetSymbolAddress((void**)&agg,   g_agg);
    cudaGetSymbolAddress((void**)&featA, g_featA);
    cudaGetSymbolAddress((void**)&featB, g_featB);
    cudaGetSymbolAddress((void**)&hpart, g_hpart);
    cudaGetSymbolAddress((void**)&hbuf,  g_h);

    const int TPB = 256;
    int nodeBlocks = (N_NODES + TPB - 1) / TPB;
    int edgeBlocks4 = (N_EDGES / 4 + TPB - 1) / TPB;
    int warpNodeBlocks = (N_NODES * 32 + TPB - 1) / TPB;
    int halfNodeBlocks = (N_NODES * 16 + TPB - 1) / TPB;
    int mBlocks = (N_NODES + 127) / 128;

    init_detect_kernel<<<nodeBlocks, TPB>>>(ei);
    histo_kernel<<<edgeBlocks4, TPB>>>(ei);
    scan_node_init_kernel<<<1, 1024>>>();
    fill_kernel<<<edgeBlocks4, TPB>>>(ei);

    aggregate16_kernel<<<halfNodeBlocks, TPB>>>(x, agg);
    gemm_tf32_kernel<64, 1><<<dim3(1, mBlocks), 256>>>(agg, W1, b1, featA, nullptr, nullptr,
                                                       N_NODES, 16, 64, 1);
    aggregate_half_kernel<64><<<warpNodeBlocks, TPB>>>(featA, agg);
    gemm_tf32_kernel<128, 1><<<dim3(1, mBlocks), 256>>>(agg, W2, b2, featB, nullptr, nullptr,
                                                        N_NODES, 64, 128, 1);
    aggregate_half_kernel<128><<<warpNodeBlocks, TPB>>>(featB, agg);
    gemm_tf32_kernel<128, 1><<<dim3(2, mBlocks), 256>>>(agg, W3, b3, featA, nullptr, nullptr,
                                                        N_NODES, 128, 256, 1);
    aggregate_half_kernel<256><<<warpNodeBlocks, TPB>>>(featA, agg);
    gemm_tf32_kernel<128, 2><<<dim3(4, mBlocks), 256>>>(agg, W4, b4, nullptr, W5, hpart,
                                                        N_NODES, 256, 512, 1);
    hreduce_kernel<<<nodeBlocks, TPB>>>(hpart, hbuf);
    final_agg_kernel<<<nodeBlocks, TPB>>>(hbuf, b5, out);
}

// round 9
// speedup vs baseline: 2.6010x; 1.1992x over previous
#include <cuda_runtime.h>
#include <cuda_fp16.h>
#include <math.h>
#include <stdint.h>

#define N_NODES 20000
#define N_EDGES 320000

// ---------------- device scratch ----------------
__device__ int   g_e64;
__device__ int   g_cnt[N_NODES];
__device__ int   g_ptr[N_NODES + 1];
__device__ int   g_cur[N_NODES];
__device__ __align__(16) int2  g_srcw[N_EDGES];
__device__ float g_deg[N_NODES];
__device__ float g_dinv[N_NODES];
__device__ __align__(256) __half g_aggh[N_NODES * 256];     // GEMM A input (fp16)
__device__ __align__(256) __half g_featA[N_NODES * 256];    // L1 out (pad situation) / L3 out (256)
__device__ __align__(256) __half g_featB[N_NODES * 128];    // L2 out (128)
__device__ __align__(16) __half g_w1h[32 * 64];             // W1 zero-padded K 16->32
__device__ __align__(16) __half g_w2h[64 * 128];
__device__ __align__(16) __half g_w3h[128 * 256];
__device__ __align__(16) __half g_w4h[256 * 512];
__device__ float g_hpart[8 * N_NODES];
__device__ float g_h[N_NODES];

__device__ __forceinline__ int edge_at(const void* e, long long idx) {
    if (g_e64) return (int)((const long long*)e)[idx];
    return ((const int*)e)[idx];
}

// ---------------- prep: zero cnt + dtype detect + weight fp16 conversion ----------------
__global__ void prep_kernel(const void* e, const float* __restrict__ W1,
                            const float* __restrict__ W2, const float* __restrict__ W3,
                            const float* __restrict__ W4) {
    int i = blockIdx.x * blockDim.x + threadIdx.x;
    if (i < N_NODES) g_cnt[i] = 0;
    if (i == 0) {
        const long long* p = (const long long*)e;
        bool ok = true;
#pragma unroll
        for (int k = 0; k < 8; k++) {
            long long v = p[k];
            if (v < 0 || v >= N_NODES) ok = false;
        }
        g_e64 = ok ? 1 : 0;
    }
    if (i < 2048) {                       // W1 padded: [32][64], rows >=16 zero
        int k = i >> 6, n = i & 63;
        g_w1h[i] = __float2half(k < 16 ? W1[k * 64 + n] : 0.f);
    } else if (i < 2048 + 8192) {
        int j = i - 2048;  g_w2h[j] = __float2half(W2[j]);
    } else if (i < 2048 + 8192 + 32768) {
        int j = i - 10240; g_w3h[j] = __float2half(W3[j]);
    } else if (i < 2048 + 8192 + 32768 + 131072) {
        int j = i - 43008; g_w4h[j] = __float2half(W4[j]);
    }
}

__global__ void histo_kernel(const void* e) {
    int i = blockIdx.x * blockDim.x + threadIdx.x;
    if (i < N_EDGES) atomicAdd(&g_cnt[edge_at(e, (long long)N_EDGES + i)], 1);
}

__global__ void scan_node_init_kernel() {
    const int C = (N_NODES + 1023) / 1024;   // 20
    int t = threadIdx.x;
    int base = t * C;
    int local[C];
    int sum = 0;
#pragma unroll
    for (int c = 0; c < C; c++) {
        int i = base + c;
        int v = (i < N_NODES) ? g_cnt[i] : 0;
        sum += v;
        local[c] = sum;
    }
    int lane = t & 31, wid = t >> 5;
    int incl = sum;
#pragma unroll
    for (int o = 1; o < 32; o <<= 1) {
        int y = __shfl_up_sync(0xffffffffu, incl, o);
        if (lane >= o) incl += y;
    }
    __shared__ int ws[32];
    if (lane == 31) ws[wid] = incl;
    __syncthreads();
    if (wid == 0) {
        int v = ws[lane];
        int iv = v;
#pragma unroll
        for (int o = 1; o < 32; o <<= 1) {
            int y = __shfl_up_sync(0xffffffffu, iv, o);
            if (lane >= o) iv += y;
        }
        ws[lane] = iv - v;
    }
    __syncthreads();
    int offset = ws[wid] + (incl - sum);
    if (t == 0) g_ptr[0] = 0;
#pragma unroll
    for (int c = 0; c < C; c++) {
        int i = base + c;
        if (i >= N_NODES) break;
        g_ptr[i + 1] = offset + local[c];
        g_cur[i] = offset + (c ? local[c - 1] : 0);
        int v = local[c] - (c ? local[c - 1] : 0);
        float d = (float)(v + 1);
        g_deg[i] = d;
        g_dinv[i] = rsqrtf(d);
    }
}

__global__ void fill_kernel(const void* e) {
    int i = blockIdx.x * blockDim.x + threadIdx.x;
    if (i < N_EDGES) {
        int src = edge_at(e, i);
        int dst = edge_at(e, (long long)N_EDGES + i);
        int pos = atomicAdd(&g_cur[dst], 1);
        g_srcw[pos] = make_int2(src, __float_as_int(g_dinv[src]));
    }
}

// ---------------- aggregation from fp16 features -> fp16 A ----------------
template <int D>
__global__ void aggregate_half_kernel(const __half* __restrict__ X, __half* __restrict__ A) {
    int node = (blockIdx.x * blockDim.x + threadIdx.x) >> 5;
    int lane = threadIdx.x & 31;
    if (node >= N_NODES) return;
    int beg = g_ptr[node], end = g_ptr[node + 1];
    float di = g_dinv[node];
    float selfw = di * di;
    float scale = 1.0f / g_deg[node];
    constexpr int V2 = D / 64;

    float2 acc[V2];
#pragma unroll
    for (int r = 0; r < V2; r++) acc[r] = make_float2(0.f, 0.f);

    for (int p = beg; p < end; p++) {
        int2 sw = g_srcw[p];
        float w = __int_as_float(sw.y);
        const __half2* xs = (const __half2*)(X + (long long)sw.x * D) + lane * V2;
        if constexpr (V2 == 4) {
            uint4 raw = *(const uint4*)xs;
            const __half2* hp = (const __half2*)&raw;
#pragma unroll
            for (int r = 0; r < 4; r++) {
                float2 v = __half22float2(hp[r]);
                acc[r].x += w * v.x; acc[r].y += w * v.y;
            }
        } else if constexpr (V2 == 2) {
            uint2 raw = *(const uint2*)xs;
            const __half2* hp = (const __half2*)&raw;
#pragma unroll
            for (int r = 0; r < 2; r++) {
                float2 v = __half22float2(hp[r]);
                acc[r].x += w * v.x; acc[r].y += w * v.y;
            }
        } else {
            float2 v = __half22float2(*xs);
            acc[0].x += w * v.x; acc[0].y += w * v.y;
        }
    }
    const __half2* xi = (const __half2*)(X + (long long)node * D) + lane * V2;
    __half2* ao = (__half2*)(A + (long long)node * D) + lane * V2;
#pragma unroll
    for (int r = 0; r < V2; r++) {
        float2 s = __half22float2(xi[r]);
        ao[r] = __floats2half2_rn((di * acc[r].x + selfw * s.x) * scale,
                                  (di * acc[r].y + selfw * s.y) * scale);
    }
}

// layer-1 input aggregation (fp32 x, D=16) -> half A [N][32] zero-padded
__global__ void aggregate16_kernel(const float* __restrict__ X, __half* __restrict__ A) {
    int node = (blockIdx.x * blockDim.x + threadIdx.x) >> 5;
    int lane = threadIdx.x & 31;
    if (node >= N_NODES) return;
    int beg = g_ptr[node], end = g_ptr[node + 1];
    float di = g_dinv[node];
    float acc = 0.f;
    if (lane < 16) {
        for (int p = beg; p < end; p++) {
            int2 sw = g_srcw[p];
            acc += __int_as_float(sw.y) * X[(long long)sw.x * 16 + lane];
        }
        acc = (di * acc + di * di * X[(long long)node * 16 + lane]) / g_deg[node];
    }
    A[(long long)node * 32 + lane] = __float2half(lane < 16 ? acc : 0.f);
}

// ---------------- fp16 tensor-core GEMM (HMMA m16n8k16, cp.async, ldmatrix) ----------------
__device__ __forceinline__ void mma_f16(float& c0, float& c1, float& c2, float& c3,
                                        uint32_t a0, uint32_t a1, uint32_t a2, uint32_t a3,
                                        uint32_t b0, uint32_t b1) {
    asm volatile(
        "mma.sync.aligned.m16n8k16.row.col.f32.f16.f16.f32 "
        "{%0,%1,%2,%3},{%4,%5,%6,%7},{%8,%9},{%0,%1,%2,%3};\n"
        : "+f"(c0), "+f"(c1), "+f"(c2), "+f"(c3)
        : "r"(a0), "r"(a1), "r"(a2), "r"(a3), "r"(b0), "r"(b1));
}

__device__ __forceinline__ void ldsm_x4(uint32_t& r0, uint32_t& r1, uint32_t& r2, uint32_t& r3,
                                        uint32_t addr) {
    asm volatile("ldmatrix.sync.aligned.m8n8.x4.shared.b16 {%0,%1,%2,%3}, [%4];"
                 : "=r"(r0), "=r"(r1), "=r"(r2), "=r"(r3) : "r"(addr));
}

__device__ __forceinline__ void ldsm_x4t(uint32_t& r0, uint32_t& r1, uint32_t& r2, uint32_t& r3,
                                         uint32_t addr) {
    asm volatile("ldmatrix.sync.aligned.m8n8.x4.trans.shared.b16 {%0,%1,%2,%3}, [%4];"
                 : "=r"(r0), "=r"(r1), "=r"(r2), "=r"(r3) : "r"(addr));
}

__device__ __forceinline__ void cp16(uint32_t dst, const void* src, bool pred) {
    int bytes = pred ? 16 : 0;
    asm volatile("cp.async.ca.shared.global [%0], [%1], 16, %2;\n"
                 :: "r"(dst), "l"(src), "r"(bytes));
}

// MODE: 1 = fp16 C, 2 = fused rowdot (no C)
template <int BN, int MODE>
__global__ __launch_bounds__(256)
void gemm_f16_kernel(const __half* __restrict__ A, const __half* __restrict__ B,
                     const float* __restrict__ bias, __half* __restrict__ Ch,
                     const float* __restrict__ w5, float* __restrict__ hpart,
                     int M, int K, int N) {
    constexpr int BM = 128, BK = 32;
    constexpr int ASTR = BK + 8;     // halfs; row stride 80B (16B multiple, conflict-free)
    constexpr int BSTR = BN + 8;     // 272B for BN=128
    constexpr int WN = BN / 64, WM = 8 / WN, MT = BM / (WM * 16);

    __shared__ __half Ah[2][BM][ASTR];
    __shared__ __half Bh[2][BK][BSTR];

    int tid = threadIdx.x, lane = tid & 31, warp = tid >> 5;
    int warp_m = warp % WM, warp_n = warp / WM;
    int row0 = warp_m * (MT * 16), col0 = warp_n * 64;
    int rowBase = blockIdx.y * BM, colBase = blockIdx.x * BN;

    // A copy: 4 x 16B chunks per 32-half row; 64 rows per 256-thread wave
    int ar = tid >> 2;
    int ac = (tid & 3) * 8;
    // B copy: BN halfs per row -> BN/8 chunks
    int br = tid / (BN / 8);
    int bc = (tid % (BN / 8)) * 8;

    auto issue = [&](int kt, int s) {
        int k0 = kt * BK;
#pragma unroll
        for (int i = 0; i < 2; i++) {
            int r = ar + i * 64;
            int gr = rowBase + r;
            bool ok = gr < M;
            const __half* src = A + (long long)(ok ? gr : 0) * K + k0 + ac;
            cp16((uint32_t)__cvta_generic_to_shared(&Ah[s][r][ac]), src, ok);
        }
        constexpr int RPW = 2048 / BN;           // rows per wave
#pragma unroll
        for (int i = 0; i < BK / RPW; i++) {
            int r = br + i * RPW;
            const __half* src = B + (long long)(k0 + r) * N + colBase + bc;
            cp16((uint32_t)__cvta_generic_to_shared(&Bh[s][r][bc]), src, true);
        }
        asm volatile("cp.async.commit_group;\n");
    };

    float acc[MT][8][4];
#pragma unroll
    for (int mt = 0; mt < MT; mt++)
#pragma unroll
        for (int nt = 0; nt < 8; nt++)
#pragma unroll
            for (int q = 0; q < 4; q++) acc[mt][nt][q] = 0.f;

    int lr = lane >> 2, lc = lane & 3;
    int l8 = lane & 7;
    int lhalf = (lane >> 3) & 1;     // +8 row/k offset
    int lhi = lane >> 4;             // +8 col offset
    int KT = K / BK;

    issue(0, 0);
    for (int kt = 0; kt < KT; kt++) {
        int s = kt & 1;
        if (kt + 1 < KT) {
            issue(kt + 1, 1 - s);
            asm volatile("cp.async.wait_group 1;\n");
        } else {
            asm volatile("cp.async.wait_group 0;\n");
        }
        __syncthreads();
#pragma unroll
        for (int ks = 0; ks < 2; ks++) {
            int k16 = ks * 16;
            // B frags: 4 x ldmatrix.x4.trans, each covers 2 n-tiles (16 cols)
            uint32_t bb[8][2];
#pragma unroll
            for (int pr = 0; pr < 4; pr++) {
                int n0 = col0 + pr * 16;
                uint32_t addr = (uint32_t)__cvta_generic_to_shared(
                    &Bh[s][k16 + l8 + lhalf * 8][n0 + lhi * 8]);
                ldsm_x4t(bb[2 * pr][0], bb[2 * pr][1], bb[2 * pr + 1][0], bb[2 * pr + 1][1], addr);
            }
#pragma unroll
            for (int mt = 0; mt < MT; mt++) {
                uint32_t a0, a1, a2, a3;
                uint32_t addr = (uint32_t)__cvta_generic_to_shared(
                    &Ah[s][row0 + mt * 16 + l8 + lhalf * 8][k16 + lhi * 8]);
                ldsm_x4(a0, a1, a2, a3, addr);
#pragma unroll
                for (int nt = 0; nt < 8; nt++)
                    mma_f16(acc[mt][nt][0], acc[mt][nt][1], acc[mt][nt][2], acc[mt][nt][3],
                            a0, a1, a2, a3, bb[nt][0], bb[nt][1]);
            }
        }
        __syncthreads();
    }

#pragma unroll
    for (int mt = 0; mt < MT; mt++) {
        int r1 = rowBase + row0 + mt * 16 + lr;
        int r2 = r1 + 8;
        float d1 = 0.f, d2 = 0.f;
#pragma unroll
        for (int nt = 0; nt < 8; nt++) {
            int c = colBase + col0 + nt * 8 + lc * 2;
            float bv0 = bias[c], bv1 = bias[c + 1];
            float v0 = fmaxf(acc[mt][nt][0] + bv0, 0.f);
            float v1 = fmaxf(acc[mt][nt][1] + bv1, 0.f);
            float v2 = fmaxf(acc[mt][nt][2] + bv0, 0.f);
            float v3 = fmaxf(acc[mt][nt][3] + bv1, 0.f);
            if constexpr (MODE == 2) {
                float w0 = w5[c], w1 = w5[c + 1];
                if (r1 < M) d1 += v0 * w0 + v1 * w1;
                if (r2 < M) d2 += v2 * w0 + v3 * w1;
            } else {
                if (r1 < M) *(__half2*)(Ch + (long long)r1 * N + c) = __floats2half2_rn(v0, v1);
                if (r2 < M) *(__half2*)(Ch + (long long)r2 * N + c) = __floats2half2_rn(v2, v3);
            }
        }
        if constexpr (MODE == 2) {
            d1 += __shfl_xor_sync(0xffffffffu, d1, 1);
            d1 += __shfl_xor_sync(0xffffffffu, d1, 2);
            d2 += __shfl_xor_sync(0xffffffffu, d2, 1);
            d2 += __shfl_xor_sync(0xffffffffu, d2, 2);
            int slot = blockIdx.x * WN + warp_n;
            if (lc == 0) {
                if (r1 < M) hpart[slot * N_NODES + r1] = d1;
                if (r2 < M) hpart[slot * N_NODES + r2] = d2;
            }
        }
    }
}

// ---------------- layer-5 reduce + add-aggregate + sigmoid ----------------
__global__ void hreduce_kernel(const float* __restrict__ hpart, float* __restrict__ h) {
    int i = blockIdx.x * blockDim.x + threadIdx.x;
    if (i < N_NODES) {
        float s = 0.f;
#pragma unroll
        for (int j = 0; j < 8; j++) s += hpart[j * N_NODES + i];
        h[i] = s;
    }
}

__global__ void final_agg_kernel(const float* __restrict__ h, const float* __restrict__ b5,
                                 float* __restrict__ out) {
    int i = blockIdx.x * blockDim.x + threadIdx.x;
    if (i >= N_NODES) return;
    float s = 0.f;
    int beg = g_ptr[i], end = g_ptr[i + 1];
    for (int p = beg; p < end; p++) {
        int2 sw = g_srcw[p];
        s += __int_as_float(sw.y) * h[sw.x];
    }
    float di = g_dinv[i];
    float v = di * s + di * di * h[i] + b5[0];
    out[i] = 1.f / (1.f + expf(-v));
}

// ---------------- launch ----------------
extern "C" void kernel_launch(void* const* d_in, const int* in_sizes, int n_in,
                              void* d_out, int out_size) {
    const float* x  = (const float*)d_in[0];
    const void*  ei = d_in[1];
    const float* W1 = (const float*)d_in[2],  *b1 = (const float*)d_in[3];
    const float* W2 = (const float*)d_in[4],  *b2 = (const float*)d_in[5];
    const float* W3 = (const float*)d_in[6],  *b3 = (const float*)d_in[7];
    const float* W4 = (const float*)d_in[8],  *b4 = (const float*)d_in[9];
    const float* W5 = (const float*)d_in[10], *b5 = (const float*)d_in[11];
    float* out = (float*)d_out;

    __half *aggh, *featA, *featB, *w1h, *w2h, *w3h, *w4h;
    float *hpart, *hbuf;
    cudaGetSymbolAddress((void**)&aggh,  g_aggh);
    cudaGetSymbolAddress((void**)&featA, g_featA);
    cudaGetSymbolAddress((void**)&featB, g_featB);
    cudaGetSymbolAddress((void**)&w1h,   g_w1h);
    cudaGetSymbolAddress((void**)&w2h,   g_w2h);
    cudaGetSymbolAddress((void**)&w3h,   g_w3h);
    cudaGetSymbolAddress((void**)&w4h,   g_w4h);
    cudaGetSymbolAddress((void**)&hpart, g_hpart);
    cudaGetSymbolAddress((void**)&hbuf,  g_h);

    const int TPB = 256;
    int nodeBlocks = (N_NODES + TPB - 1) / TPB;
    int edgeBlocks = (N_EDGES + TPB - 1) / TPB;
    int warpNodeBlocks = (N_NODES * 32 + TPB - 1) / TPB;
    int prepBlocks = (174080 + TPB - 1) / TPB;
    int mBlocks = (N_NODES + 127) / 128;

    prep_kernel<<<prepBlocks, TPB>>>(ei, W1, W2, W3, W4);
    histo_kernel<<<edgeBlocks, TPB>>>(ei);
    scan_node_init_kernel<<<1, 1024>>>();
    fill_kernel<<<edgeBlocks, TPB>>>(ei);

    aggregate16_kernel<<<warpNodeBlocks, TPB>>>(x, aggh);
    gemm_f16_kernel<64, 1><<<dim3(1, mBlocks), 256>>>(aggh, w1h, b1, featA, nullptr, nullptr,
                                                      N_NODES, 32, 64);
    aggregate_half_kernel<64><<<warpNodeBlocks, TPB>>>(featA, aggh);
    gemm_f16_kernel<128, 1><<<dim3(1, mBlocks), 256>>>(aggh, w2h, b2, featB, nullptr, nullptr,
                                                       N_NODES, 64, 128);
    aggregate_half_kernel<128><<<warpNodeBlocks, TPB>>>(featB, aggh);
    gemm_f16_kernel<128, 1><<<dim3(2, mBlocks), 256>>>(aggh, w3h, b3, featA, nullptr, nullptr,
                                                       N_NODES, 128, 256);
    aggregate_half_kernel<256><<<warpNodeBlocks, TPB>>>(featA, aggh);
    gemm_f16_kernel<128, 2><<<dim3(4, mBlocks), 256>>>(aggh, w4h, b4, nullptr, W5, hpart,
                                                       N_NODES, 256, 512);
    hreduce_kernel<<<nodeBlocks, TPB>>>(hpart, hbuf);
    final_agg_kernel<<<nodeBlocks, TPB>>>(hbuf, b5, out);
}

// round 11
// speedup vs baseline: 2.6239x; 1.0088x over previous
#include <cuda_runtime.h>
#include <cuda_fp16.h>
#include <math.h>
#include <stdint.h>

#define N_NODES 20000
#define N_EDGES 320000

// ---------------- device scratch ----------------
__device__ int   g_e64;
__device__ int   g_cnt[N_NODES];
__device__ int   g_ptr[N_NODES + 1];
__device__ int   g_cur[N_NODES];
__device__ __align__(16) int2  g_srcw[N_EDGES];
__device__ float g_deg[N_NODES];
__device__ float g_dinv[N_NODES];
__device__ __align__(256) __half g_aggh[N_NODES * 256];
__device__ __align__(256) __half g_featA[N_NODES * 256];
__device__ __align__(256) __half g_featB[N_NODES * 128];
__device__ __align__(16) __half g_w1h[32 * 64];
__device__ __align__(16) __half g_w2h[64 * 128];
__device__ __align__(16) __half g_w3h[128 * 256];
__device__ __align__(16) __half g_w4h[256 * 512];
__device__ float g_hpart[8 * N_NODES];
__device__ float g_h[N_NODES];

__device__ __forceinline__ int edge_at(const void* e, long long idx) {
    if (g_e64) return (int)((const long long*)e)[idx];
    return ((const int*)e)[idx];
}

// ---------------- prep: zero cnt + dtype detect + weight fp16 conversion ----------------
__global__ void prep_kernel(const void* e, const float* __restrict__ W1,
                            const float* __restrict__ W2, const float* __restrict__ W3,
                            const float* __restrict__ W4) {
    int i = blockIdx.x * blockDim.x + threadIdx.x;
    if (i < N_NODES) g_cnt[i] = 0;
    if (i == 0) {
        const long long* p = (const long long*)e;
        bool ok = true;
#pragma unroll
        for (int k = 0; k < 8; k++) {
            long long v = p[k];
            if (v < 0 || v >= N_NODES) ok = false;
        }
        g_e64 = ok ? 1 : 0;
    }
    if (i < 2048) {
        int k = i >> 6, n = i & 63;
        g_w1h[i] = __float2half(k < 16 ? W1[k * 64 + n] : 0.f);
    } else if (i < 2048 + 8192) {
        int j = i - 2048;  g_w2h[j] = __float2half(W2[j]);
    } else if (i < 2048 + 8192 + 32768) {
        int j = i - 10240; g_w3h[j] = __float2half(W3[j]);
    } else if (i < 2048 + 8192 + 32768 + 131072) {
        int j = i - 43008; g_w4h[j] = __float2half(W4[j]);
    }
}

__global__ void histo_kernel(const void* e) {
    int i0 = (blockIdx.x * blockDim.x + threadIdx.x) * 2;
    int d0 = -1, d1 = -1;
    if (i0 < N_EDGES)     d0 = edge_at(e, (long long)N_EDGES + i0);
    if (i0 + 1 < N_EDGES) d1 = edge_at(e, (long long)N_EDGES + i0 + 1);
    if (d0 >= 0) atomicAdd(&g_cnt[d0], 1);
    if (d1 >= 0) atomicAdd(&g_cnt[d1], 1);
}

__global__ void scan_node_init_kernel() {
    const int C = (N_NODES + 1023) / 1024;   // 20
    int t = threadIdx.x;
    int base = t * C;
    int local[C];
    int sum = 0;
#pragma unroll
    for (int c = 0; c < C; c++) {
        int i = base + c;
        int v = (i < N_NODES) ? g_cnt[i] : 0;
        sum += v;
        local[c] = sum;
    }
    int lane = t & 31, wid = t >> 5;
    int incl = sum;
#pragma unroll
    for (int o = 1; o < 32; o <<= 1) {
        int y = __shfl_up_sync(0xffffffffu, incl, o);
        if (lane >= o) incl += y;
    }
    __shared__ int ws[32];
    if (lane == 31) ws[wid] = incl;
    __syncthreads();
    if (wid == 0) {
        int v = ws[lane];
        int iv = v;
#pragma unroll
        for (int o = 1; o < 32; o <<= 1) {
            int y = __shfl_up_sync(0xffffffffu, iv, o);
            if (lane >= o) iv += y;
        }
        ws[lane] = iv - v;
    }
    __syncthreads();
    int offset = ws[wid] + (incl - sum);
    if (t == 0) g_ptr[0] = 0;
#pragma unroll
    for (int c = 0; c < C; c++) {
        int i = base + c;
        if (i >= N_NODES) break;
        g_ptr[i + 1] = offset + local[c];
        g_cur[i] = offset + (c ? local[c - 1] : 0);
        int v = local[c] - (c ? local[c - 1] : 0);
        float d = (float)(v + 1);
        g_deg[i] = d;
        g_dinv[i] = rsqrtf(d);
    }
}

__global__ void fill_kernel(const void* e) {
    int i0 = (blockIdx.x * blockDim.x + threadIdx.x) * 2;
    int s0 = 0, s1 = 0, p0 = -1, p1 = -1;
    if (i0 < N_EDGES) {
        s0 = edge_at(e, i0);
        int d0 = edge_at(e, (long long)N_EDGES + i0);
        p0 = atomicAdd(&g_cur[d0], 1);
    }
    if (i0 + 1 < N_EDGES) {
        s1 = edge_at(e, i0 + 1);
        int d1 = edge_at(e, (long long)N_EDGES + i0 + 1);
        p1 = atomicAdd(&g_cur[d1], 1);
    }
    if (p0 >= 0) g_srcw[p0] = make_int2(s0, __float_as_int(g_dinv[s0]));
    if (p1 >= 0) g_srcw[p1] = make_int2(s1, __float_as_int(g_dinv[s1]));
}

// ---------------- aggregation from fp16 features -> fp16 A (4x unrolled MLP) ----------------
template <int D>
__global__ void aggregate_half_kernel(const __half* __restrict__ X, __half* __restrict__ A) {
    int node = (blockIdx.x * blockDim.x + threadIdx.x) >> 5;
    int lane = threadIdx.x & 31;
    if (node >= N_NODES) return;
    int beg = g_ptr[node], end = g_ptr[node + 1];
    float di = g_dinv[node];
    float selfw = di * di;
    float scale = 1.0f / g_deg[node];
    constexpr int V2 = D / 64;

    float2 acc[V2];
#pragma unroll
    for (int r = 0; r < V2; r++) acc[r] = make_float2(0.f, 0.f);

    auto rowptr = [&](int src) {
        return (const __half2*)(X + (long long)src * D) + lane * V2;
    };
    auto accum = [&](const __half2* hp, float w) {
#pragma unroll
        for (int r = 0; r < V2; r++) {
            float2 v = __half22float2(hp[r]);
            acc[r].x += w * v.x; acc[r].y += w * v.y;
        }
    };

    int p = beg;
    int end4 = beg + ((end - beg) & ~3);
    for (; p < end4; p += 4) {
        int2 sw0 = g_srcw[p], sw1 = g_srcw[p + 1], sw2 = g_srcw[p + 2], sw3 = g_srcw[p + 3];
        if constexpr (V2 == 4) {
            uint4 r0 = *(const uint4*)rowptr(sw0.x);
            uint4 r1 = *(const uint4*)rowptr(sw1.x);
            uint4 r2 = *(const uint4*)rowptr(sw2.x);
            uint4 r3 = *(const uint4*)rowptr(sw3.x);
            accum((const __half2*)&r0, __int_as_float(sw0.y));
            accum((const __half2*)&r1, __int_as_float(sw1.y));
            accum((const __half2*)&r2, __int_as_float(sw2.y));
            accum((const __half2*)&r3, __int_as_float(sw3.y));
        } else if constexpr (V2 == 2) {
            uint2 r0 = *(const uint2*)rowptr(sw0.x);
            uint2 r1 = *(const uint2*)rowptr(sw1.x);
            uint2 r2 = *(const uint2*)rowptr(sw2.x);
            uint2 r3 = *(const uint2*)rowptr(sw3.x);
            accum((const __half2*)&r0, __int_as_float(sw0.y));
            accum((const __half2*)&r1, __int_as_float(sw1.y));
            accum((const __half2*)&r2, __int_as_float(sw2.y));
            accum((const __half2*)&r3, __int_as_float(sw3.y));
        } else {
            __half2 r0 = *rowptr(sw0.x), r1 = *rowptr(sw1.x);
            __half2 r2 = *rowptr(sw2.x), r3 = *rowptr(sw3.x);
            accum(&r0, __int_as_float(sw0.y));
            accum(&r1, __int_as_float(sw1.y));
            accum(&r2, __int_as_float(sw2.y));
            accum(&r3, __int_as_float(sw3.y));
        }
    }
    for (; p < end; p++) {
        int2 sw = g_srcw[p];
        if constexpr (V2 == 4) {
            uint4 r0 = *(const uint4*)rowptr(sw.x);
            accum((const __half2*)&r0, __int_as_float(sw.y));
        } else if constexpr (V2 == 2) {
            uint2 r0 = *(const uint2*)rowptr(sw.x);
            accum((const __half2*)&r0, __int_as_float(sw.y));
        } else {
            __half2 r0 = *rowptr(sw.x);
            accum(&r0, __int_as_float(sw.y));
        }
    }

    const __half2* xi = (const __half2*)(X + (long long)node * D) + lane * V2;
    __half2* ao = (__half2*)(A + (long long)node * D) + lane * V2;
#pragma unroll
    for (int r = 0; r < V2; r++) {
        float2 s = __half22float2(xi[r]);
        ao[r] = __floats2half2_rn((di * acc[r].x + selfw * s.x) * scale,
                                  (di * acc[r].y + selfw * s.y) * scale);
    }
}

// layer-1 input aggregation (fp32 x, D=16) -> half A [N][32] zero-padded
__global__ void aggregate16_kernel(const float* __restrict__ X, __half* __restrict__ A) {
    int node = (blockIdx.x * blockDim.x + threadIdx.x) >> 5;
    int lane = threadIdx.x & 31;
    if (node >= N_NODES) return;
    int beg = g_ptr[node], end = g_ptr[node + 1];
    float di = g_dinv[node];
    float acc = 0.f;
    int lidx = lane & 15;
    int p = beg;
    int end4 = beg + ((end - beg) & ~3);
    for (; p < end4; p += 4) {
        int2 sw0 = g_srcw[p], sw1 = g_srcw[p + 1], sw2 = g_srcw[p + 2], sw3 = g_srcw[p + 3];
        float v0 = X[(long long)sw0.x * 16 + lidx];
        float v1 = X[(long long)sw1.x * 16 + lidx];
        float v2 = X[(long long)sw2.x * 16 + lidx];
        float v3 = X[(long long)sw3.x * 16 + lidx];
        acc += __int_as_float(sw0.y) * v0 + __int_as_float(sw1.y) * v1
             + __int_as_float(sw2.y) * v2 + __int_as_float(sw3.y) * v3;
    }
    for (; p < end; p++) {
        int2 sw = g_srcw[p];
        acc += __int_as_float(sw.y) * X[(long long)sw.x * 16 + lidx];
    }
    acc = (di * acc + di * di * X[(long long)node * 16 + lidx]) / g_deg[node];
    A[(long long)node * 32 + lane] = __float2half(lane < 16 ? acc : 0.f);
}

// ---------------- fp16 tensor-core GEMM (HMMA m16n8k16, cp.async, ldmatrix) ----------------
__device__ __forceinline__ void mma_f16(float& c0, float& c1, float& c2, float& c3,
                                        uint32_t a0, uint32_t a1, uint32_t a2, uint32_t a3,
                                        uint32_t b0, uint32_t b1) {
    asm volatile(
        "mma.sync.aligned.m16n8k16.row.col.f32.f16.f16.f32 "
        "{%0,%1,%2,%3},{%4,%5,%6,%7},{%8,%9},{%0,%1,%2,%3};\n"
        : "+f"(c0), "+f"(c1), "+f"(c2), "+f"(c3)
        : "r"(a0), "r"(a1), "r"(a2), "r"(a3), "r"(b0), "r"(b1));
}

__device__ __forceinline__ void ldsm_x4(uint32_t& r0, uint32_t& r1, uint32_t& r2, uint32_t& r3,
                                        uint32_t addr) {
    asm volatile("ldmatrix.sync.aligned.m8n8.x4.shared.b16 {%0,%1,%2,%3}, [%4];"
                 : "=r"(r0), "=r"(r1), "=r"(r2), "=r"(r3) : "r"(addr));
}

__device__ __forceinline__ void ldsm_x4t(uint32_t& r0, uint32_t& r1, uint32_t& r2, uint32_t& r3,
                                         uint32_t addr) {
    asm volatile("ldmatrix.sync.aligned.m8n8.x4.trans.shared.b16 {%0,%1,%2,%3}, [%4];"
                 : "=r"(r0), "=r"(r1), "=r"(r2), "=r"(r3) : "r"(addr));
}

__device__ __forceinline__ void cp16(uint32_t dst, const void* src, bool pred) {
    int bytes = pred ? 16 : 0;
    asm volatile("cp.async.ca.shared.global [%0], [%1], 16, %2;\n"
                 :: "r"(dst), "l"(src), "r"(bytes));
}

// MODE: 1 = fp16 C, 2 = fused rowdot (no C)
template <int BN, int MODE>
__global__ __launch_bounds__(256)
void gemm_f16_kernel(const __half* __restrict__ A, const __half* __restrict__ B,
                     const float* __restrict__ bias, __half* __restrict__ Ch,
                     const float* __restrict__ w5, float* __restrict__ hpart,
                     int M, int K, int N) {
    constexpr int BM = 128, BK = 32;
    constexpr int ASTR = BK + 8;
    constexpr int BSTR = BN + 8;
    constexpr int WN = BN / 64, WM = 8 / WN, MT = BM / (WM * 16);

    __shared__ __half Ah[2][BM][ASTR];
    __shared__ __half Bh[2][BK][BSTR];

    int tid = threadIdx.x, lane = tid & 31, warp = tid >> 5;
    int warp_m = warp % WM, warp_n = warp / WM;
    int row0 = warp_m * (MT * 16), col0 = warp_n * 64;
    int rowBase = blockIdx.y * BM, colBase = blockIdx.x * BN;

    int ar = tid >> 2;
    int ac = (tid & 3) * 8;
    int br = tid / (BN / 8);
    int bc = (tid % (BN / 8)) * 8;

    auto issue = [&](int kt, int s) {
        int k0 = kt * BK;
#pragma unroll
        for (int i = 0; i < 2; i++) {
            int r = ar + i * 64;
            int gr = rowBase + r;
            bool ok = gr < M;
            const __half* src = A + (long long)(ok ? gr : 0) * K + k0 + ac;
            cp16((uint32_t)__cvta_generic_to_shared(&Ah[s][r][ac]), src, ok);
        }
        constexpr int RPW = 2048 / BN;
#pragma unroll
        for (int i = 0; i < BK / RPW; i++) {
            int r = br + i * RPW;
            const __half* src = B + (long long)(k0 + r) * N + colBase + bc;
            cp16((uint32_t)__cvta_generic_to_shared(&Bh[s][r][bc]), src, true);
        }
        asm volatile("cp.async.commit_group;\n");
    };

    float acc[MT][8][4];
#pragma unroll
    for (int mt = 0; mt < MT; mt++)
#pragma unroll
        for (int nt = 0; nt < 8; nt++)
#pragma unroll
            for (int q = 0; q < 4; q++) acc[mt][nt][q] = 0.f;

    int lr = lane >> 2, lc = lane & 3;
    int l8 = lane & 7;
    int lhalf = (lane >> 3) & 1;
    int lhi = lane >> 4;
    int KT = K / BK;

    issue(0, 0);
    for (int kt = 0; kt < KT; kt++) {
        int s = kt & 1;
        if (kt + 1 < KT) {
            issue(kt + 1, 1 - s);
            asm volatile("cp.async.wait_group 1;\n");
        } else {
            asm volatile("cp.async.wait_group 0;\n");
        }
        __syncthreads();
#pragma unroll
        for (int ks = 0; ks < 2; ks++) {
            int k16 = ks * 16;
            uint32_t bb[8][2];
#pragma unroll
            for (int pr = 0; pr < 4; pr++) {
                int n0 = col0 + pr * 16;
                uint32_t addr = (uint32_t)__cvta_generic_to_shared(
                    &Bh[s][k16 + l8 + lhalf * 8][n0 + lhi * 8]);
                ldsm_x4t(bb[2 * pr][0], bb[2 * pr][1], bb[2 * pr + 1][0], bb[2 * pr + 1][1], addr);
            }
#pragma unroll
            for (int mt = 0; mt < MT; mt++) {
                uint32_t a0, a1, a2, a3;
                uint32_t addr = (uint32_t)__cvta_generic_to_shared(
                    &Ah[s][row0 + mt * 16 + l8 + lhalf * 8][k16 + lhi * 8]);
                ldsm_x4(a0, a1, a2, a3, addr);
#pragma unroll
                for (int nt = 0; nt < 8; nt++)
                    mma_f16(acc[mt][nt][0], acc[mt][nt][1], acc[mt][nt][2], acc[mt][nt][3],
                            a0, a1, a2, a3, bb[nt][0], bb[nt][1]);
            }
        }
        __syncthreads();
    }

#pragma unroll
    for (int mt = 0; mt < MT; mt++) {
        int r1 = rowBase + row0 + mt * 16 + lr;
        int r2 = r1 + 8;
        float d1 = 0.f, d2 = 0.f;
#pragma unroll
        for (int nt = 0; nt < 8; nt++) {
            int c = colBase + col0 + nt * 8 + lc * 2;
            float bv0 = bias[c], bv1 = bias[c + 1];
            float v0 = fmaxf(acc[mt][nt][0] + bv0, 0.f);
            float v1 = fmaxf(acc[mt][nt][1] + bv1, 0.f);
            float v2 = fmaxf(acc[mt][nt][2] + bv0, 0.f);
            float v3 = fmaxf(acc[mt][nt][3] + bv1, 0.f);
            if constexpr (MODE == 2) {
                float w0 = w5[c], w1 = w5[c + 1];
                if (r1 < M) d1 += v0 * w0 + v1 * w1;
                if (r2 < M) d2 += v2 * w0 + v3 * w1;
            } else {
                if (r1 < M) *(__half2*)(Ch + (long long)r1 * N + c) = __floats2half2_rn(v0, v1);
                if (r2 < M) *(__half2*)(Ch + (long long)r2 * N + c) = __floats2half2_rn(v2, v3);
            }
        }
        if constexpr (MODE == 2) {
            d1 += __shfl_xor_sync(0xffffffffu, d1, 1);
            d1 += __shfl_xor_sync(0xffffffffu, d1, 2);
            d2 += __shfl_xor_sync(0xffffffffu, d2, 1);
            d2 += __shfl_xor_sync(0xffffffffu, d2, 2);
            int slot = blockIdx.x * WN + warp_n;
            if (lc == 0) {
                if (r1 < M) hpart[slot * N_NODES + r1] = d1;
                if (r2 < M) hpart[slot * N_NODES + r2] = d2;
            }
        }
    }
}

// ---------------- layer-5 reduce + add-aggregate + sigmoid ----------------
__global__ void hreduce_kernel(const float* __restrict__ hpart, float* __restrict__ h) {
    int i = blockIdx.x * blockDim.x + threadIdx.x;
    if (i < N_NODES) {
        float s = 0.f;
#pragma unroll
        for (int j = 0; j < 8; j++) s += hpart[j * N_NODES + i];
        h[i] = s;
    }
}

__global__ void final_agg_kernel(const float* __restrict__ h, const float* __restrict__ b5,
                                 float* __restrict__ out) {
    int i = blockIdx.x * blockDim.x + threadIdx.x;
    if (i >= N_NODES) return;
    float s = 0.f;
    int beg = g_ptr[i], end = g_ptr[i + 1];
    int p = beg;
    int end4 = beg + ((end - beg) & ~3);
    for (; p < end4; p += 4) {
        int2 sw0 = g_srcw[p], sw1 = g_srcw[p + 1], sw2 = g_srcw[p + 2], sw3 = g_srcw[p + 3];
        float h0 = h[sw0.x], h1 = h[sw1.x], h2 = h[sw2.x], h3 = h[sw3.x];
        s += __int_as_float(sw0.y) * h0 + __int_as_float(sw1.y) * h1
           + __int_as_float(sw2.y) * h2 + __int_as_float(sw3.y) * h3;
    }
    for (; p < end; p++) {
        int2 sw = g_srcw[p];
        s += __int_as_float(sw.y) * h[sw.x];
    }
    float di = g_dinv[i];
    float v = di * s + di * di * h[i] + b5[0];
    out[i] = 1.f / (1.f + expf(-v));
}

// ---------------- launch ----------------
extern "C" void kernel_launch(void* const* d_in, const int* in_sizes, int n_in,
                              void* d_out, int out_size) {
    const float* x  = (const float*)d_in[0];
    const void*  ei = d_in[1];
    const float* W1 = (const float*)d_in[2],  *b1 = (const float*)d_in[3];
    const float* W2 = (const float*)d_in[4],  *b2 = (const float*)d_in[5];
    const float* W3 = (const float*)d_in[6],  *b3 = (const float*)d_in[7];
    const float* W4 = (const float*)d_in[8],  *b4 = (const float*)d_in[9];
    const float* W5 = (const float*)d_in[10], *b5 = (const float*)d_in[11];
    float* out = (float*)d_out;

    __half *aggh, *featA, *featB, *w1h, *w2h, *w3h, *w4h;
    float *hpart, *hbuf;
    cudaGetSymbolAddress((void**)&aggh,  g_aggh);
    cudaGetSymbolAddress((void**)&featA, g_featA);
    cudaGetSymbolAddress((void**)&featB, g_featB);
    cudaGetSymbolAddress((void**)&w1h,   g_w1h);
    cudaGetSymbolAddress((void**)&w2h,   g_w2h);
    cudaGetSymbolAddress((void**)&w3h,   g_w3h);
    cudaGetSymbolAddress((void**)&w4h,   g_w4h);
    cudaGetSymbolAddress((void**)&hpart, g_hpart);
    cudaGetSymbolAddress((void**)&hbuf,  g_h);

    const int TPB = 256;
    int nodeBlocks = (N_NODES + TPB - 1) / TPB;
    int edgeBlocks2 = (N_EDGES / 2 + TPB - 1) / TPB;
    int warpNodeBlocks = (N_NODES * 32 + TPB - 1) / TPB;
    int prepBlocks = (174080 + TPB - 1) / TPB;
    int mBlocks = (N_NODES + 127) / 128;

    prep_kernel<<<prepBlocks, TPB>>>(ei, W1, W2, W3, W4);
    histo_kernel<<<edgeBlocks2, TPB>>>(ei);
    scan_node_init_kernel<<<1, 1024>>>();
    fill_kernel<<<edgeBlocks2, TPB>>>(ei);

    aggregate16_kernel<<<warpNodeBlocks, TPB>>>(x, aggh);
    gemm_f16_kernel<64, 1><<<dim3(1, mBlocks), 256>>>(aggh, w1h, b1, featA, nullptr, nullptr,
                                                      N_NODES, 32, 64);
    aggregate_half_kernel<64><<<warpNodeBlocks, TPB>>>(featA, aggh);
    gemm_f16_kernel<128, 1><<<dim3(1, mBlocks), 256>>>(aggh, w2h, b2, featB, nullptr, nullptr,
                                                       N_NODES, 64, 128);
    aggregate_half_kernel<128><<<warpNodeBlocks, TPB>>>(featB, aggh);
    gemm_f16_kernel<128, 1><<<dim3(2, mBlocks), 256>>>(aggh, w3h, b3, featA, nullptr, nullptr,
                                                       N_NODES, 128, 256);
    aggregate_half_kernel<256><<<warpNodeBlocks, TPB>>>(featA, aggh);
    gemm_f16_kernel<128, 2><<<dim3(4, mBlocks), 256>>>(aggh, w4h, b4, nullptr, W5, hpart,
                                                       N_NODES, 256, 512);
    hreduce_kernel<<<nodeBlocks, TPB>>>(hpart, hbuf);
    final_agg_kernel<<<nodeBlocks, TPB>>>(hbuf, b5, out);
}